// round 13
// baseline (speedup 1.0000x reference)
#include <cuda_runtime.h>
#include <cuda_bf16.h>
#include <cstdint>

#define BB 128
#define SSEQ 16
#define TT 256
#define ZZ 512
#define HC 1024
#define EE 512
#define HD 1024
#define VV 1024
#define NBLK 128

// ---------------- scratch (device globals; zero-init at module load) ----------------
__device__ float g_zero[BB * HD];                       // never written: stays zero (also bf16 zero rows)
__device__ float g_gxc[SSEQ * BB * 4 * HC];             // perm gate order
__device__ float g_gxe[SSEQ * BB * 4 * HD];             // perm
__device__ float g_gx[TT * BB * 4 * HD];                // perm
__device__ float g_bsum_p[3 * 4 * HD];
// bf16 h history (hi/lo split), shared across the three recurrences (serial launches)
__device__ __align__(16) __nv_bfloat16 g_hhi[TT * BB * HD];
__device__ __align__(16) __nv_bfloat16 g_hlo[TT * BB * HD];
// bf16 hi/lo activations
__device__ __align__(16) __nv_bfloat16 g_zhi[BB * SSEQ * ZZ];
__device__ __align__(16) __nv_bfloat16 g_zlo[BB * SSEQ * ZZ];
__device__ __align__(16) __nv_bfloat16 g_xhi[BB * TT * VV];
__device__ __align__(16) __nv_bfloat16 g_xlo[BB * TT * VV];
__device__ __align__(16) __nv_bfloat16 g_cinhi[SSEQ * BB * HC];
__device__ __align__(16) __nv_bfloat16 g_cinlo[SSEQ * BB * HC];
__device__ __align__(16) __nv_bfloat16 g_embhi[SSEQ * BB * EE];
__device__ __align__(16) __nv_bfloat16 g_emblo[SSEQ * BB * EE];
// bf16 hi/lo split weights
__device__ __align__(16) __nv_bfloat16 g_fczw_hi[HC * ZZ];
__device__ __align__(16) __nv_bfloat16 g_fczw_lo[HC * ZZ];
__device__ __align__(16) __nv_bfloat16 g_fccw_hi[EE * HC];
__device__ __align__(16) __nv_bfloat16 g_fccw_lo[EE * HC];
__device__ __align__(16) __nv_bfloat16 g_cwih_hi[4 * HC * HC];
__device__ __align__(16) __nv_bfloat16 g_cwih_lo[4 * HC * HC];
__device__ __align__(16) __nv_bfloat16 g_cwhh_hi[4 * HC * HC];
__device__ __align__(16) __nv_bfloat16 g_cwhh_lo[4 * HC * HC];
__device__ __align__(16) __nv_bfloat16 g_d0wih_hi[4 * HD * VV];
__device__ __align__(16) __nv_bfloat16 g_d0wih_lo[4 * HD * VV];
__device__ __align__(16) __nv_bfloat16 g_d0wihE_hi[4 * HD * EE];
__device__ __align__(16) __nv_bfloat16 g_d0wihE_lo[4 * HD * EE];
__device__ __align__(16) __nv_bfloat16 g_d0whh_hi[4 * HD * HD];
__device__ __align__(16) __nv_bfloat16 g_d0whh_lo[4 * HD * HD];
__device__ __align__(16) __nv_bfloat16 g_d1wih_hi[4 * HD * HD];
__device__ __align__(16) __nv_bfloat16 g_d1wih_lo[4 * HD * HD];
__device__ __align__(16) __nv_bfloat16 g_d1whh_hi[4 * HD * HD];
__device__ __align__(16) __nv_bfloat16 g_d1whh_lo[4 * HD * HD];
__device__ __align__(16) __nv_bfloat16 g_outw_hi[VV * HD];
__device__ __align__(16) __nv_bfloat16 g_outw_lo[VV * HD];

// flag-array grid barrier state (zero-init; gen strictly increases within a replay,
// and flag/go writes are exact-match polled, so stale values across replays are benign)
__device__ unsigned int g_flags[NBLK];
__device__ volatile unsigned int g_go;

// ---------------- helpers ----------------
__device__ __forceinline__ float4 ldcg4(const float* p) {
    return __ldcg((const float4*)(p));
}
__device__ __forceinline__ float sigm(float x) { return 1.f / (1.f + expf(-x)); }

__device__ __forceinline__ uint32_t smem_u32(const void* p) {
    uint32_t a;
    asm("{ .reg .u64 t; cvta.to.shared.u64 t, %1; cvt.u32.u64 %0, t; }" : "=r"(a) : "l"(p));
    return a;
}
__device__ __forceinline__ uint32_t pack_bf16(__nv_bfloat16 a, __nv_bfloat16 b) {
    return (uint32_t)__bfloat16_as_ushort(a) | ((uint32_t)__bfloat16_as_ushort(b) << 16);
}
__device__ __forceinline__ void split2(float x, float y, uint32_t& hp, uint32_t& lp) {
    __nv_bfloat16 hx = __float2bfloat16(x), hy = __float2bfloat16(y);
    __nv_bfloat16 lx = __float2bfloat16(x - __bfloat162float(hx));
    __nv_bfloat16 ly = __float2bfloat16(y - __bfloat162float(hy));
    hp = pack_bf16(hx, hy);
    lp = pack_bf16(lx, ly);
}

// ---------------- mma.sync (HMMA) + cp.async primitives — baseline PTX ----------------
#define MMA_BF16(d, a, b0, b1)                                                  \
    asm volatile("mma.sync.aligned.m16n8k16.row.col.f32.bf16.bf16.f32 "         \
        "{%0,%1,%2,%3}, {%4,%5,%6,%7}, {%8,%9}, {%0,%1,%2,%3};"                 \
        : "+f"((d)[0]), "+f"((d)[1]), "+f"((d)[2]), "+f"((d)[3])                \
        : "r"((a)[0]), "r"((a)[1]), "r"((a)[2]), "r"((a)[3]), "r"(b0), "r"(b1))

#define LDMX4(r, addr)                                                          \
    asm volatile("ldmatrix.sync.aligned.m8n8.x4.shared.b16 {%0,%1,%2,%3}, [%4];" \
        : "=r"((r)[0]), "=r"((r)[1]), "=r"((r)[2]), "=r"((r)[3]) : "r"(addr))

#define CP_ASYNC16(dst, src) \
    asm volatile("cp.async.cg.shared.global [%0], [%1], 16;" :: "r"(dst), "l"(src))
#define CP_COMMIT() asm volatile("cp.async.commit_group;" ::: "memory")
#define CP_WAIT(n)  asm volatile("cp.async.wait_group %0;" :: "n"(n) : "memory")

// ---------------- HMMA GEMM: C[M,N] = gather(A)[M,K] * W[N,K]^T (+bias)(+Cin)(tanh)(split) ----
// A is PRE-SPLIT bf16 hi/lo. 128x128 tile per CTA, 8 warps (2m x 4n), K-chunk 32.
// 3 mmas per (frag,k16): hh, hl, lh. Rows of 64B; chunk-XOR swizzle ^(row&3).
// amode: 0 = A row m; 1 = z-gather (row b*SSEQ+s); 2 = prev-x gather (row b*TT+t-1, zeros t==0).
// Cin: row (t>>4)*BB+b. cmode: 0 = row m; 1 = row (b*TT+t). act: tanh. Chi/Clo: bf16 split out.
#define MST 32768
__global__ __launch_bounds__(256, 2)
void gemm_mma(const __nv_bfloat16* __restrict__ Ahi, const __nv_bfloat16* __restrict__ Alo,
              const __nv_bfloat16* __restrict__ Whi, const __nv_bfloat16* __restrict__ Wlo,
              const float* __restrict__ bias, const float* __restrict__ Cin,
              float* __restrict__ C,
              __nv_bfloat16* __restrict__ Chi, __nv_bfloat16* __restrict__ Clo,
              int K, int N, int amode, int cmode, int act)
{
    extern __shared__ char sm[];
    const uint32_t sb = smem_u32(sm);
    const int tid = threadIdx.x;
    const int lane = tid & 31;
    const int wid = tid >> 5;
    const int warp_m = wid & 1;
    const int warp_n = wid >> 1;
    const int m0 = blockIdx.y << 7;
    const int n0 = blockIdx.x << 7;

    const int lrow = tid >> 1;
    const int half = tid & 1;

    // A row resolution (bf16 pre-split)
    size_t arow_off;
    bool azero = false;
    {
        int m = m0 + lrow;
        if (amode == 0) {
            arow_off = (size_t)m * K;
        } else if (amode == 1) {
            int b = m & 127, s = m >> 7;
            arow_off = ((size_t)b * SSEQ + s) * K;
        } else {
            int t = m >> 7, b = m & 127;
            if (t == 0) { azero = true; arow_off = 0; }
            else arow_off = ((size_t)b * TT + (t - 1)) * (size_t)K;
        }
    }
    const uint4* ahrow = azero ? (const uint4*)g_zero : (const uint4*)(Ahi + arow_off);
    const uint4* alrow = azero ? (const uint4*)g_zero : (const uint4*)(Alo + arow_off);
    const uint4* whrow = (const uint4*)(Whi + (size_t)(n0 + lrow) * K);
    const uint4* wlrow = (const uint4*)(Wlo + (size_t)(n0 + lrow) * K);
    const int azstep = azero ? 0 : 1;   // frozen source for zero rows

    const uint32_t sst0 = (uint32_t)lrow * 64u + (uint32_t)(((half * 2)     ^ (lrow & 3)) << 4);
    const uint32_t sst1 = (uint32_t)lrow * 64u + (uint32_t)(((half * 2 + 1) ^ (lrow & 3)) << 4);

    uint32_t a_addr[4][2], b_addr[2][2];
    {
        int ar = warp_m * 64 + (lane & 7) + (((lane >> 3) & 1) << 3);
        int akh = lane >> 4;
        int br = warp_n * 32 + (lane & 7) + ((lane >> 4) << 3);
        int bkh = (lane >> 3) & 1;
#pragma unroll
        for (int mi = 0; mi < 4; ++mi)
#pragma unroll
            for (int kk = 0; kk < 2; ++kk) {
                int row = ar + mi * 16;
                a_addr[mi][kk] = sb + (uint32_t)row * 64u
                               + (uint32_t)((((kk << 1) | akh) ^ (row & 3)) << 4);
            }
#pragma unroll
        for (int ng = 0; ng < 2; ++ng)
#pragma unroll
            for (int kk = 0; kk < 2; ++kk) {
                int row = br + ng * 16;
                b_addr[ng][kk] = sb + 16384u + (uint32_t)row * 64u
                               + (uint32_t)((((kk << 1) | bkh) ^ (row & 3)) << 4);
            }
    }

    float acc[4][4][4];
#pragma unroll
    for (int mi = 0; mi < 4; ++mi)
#pragma unroll
        for (int nf = 0; nf < 4; ++nf)
#pragma unroll
            for (int q = 0; q < 4; ++q) acc[mi][nf][q] = 0.f;

    const int NC = K >> 5;
    uint4 pah[2], pal[2], pwh[2], pwl[2];

    // prefetch + store chunk 0
#pragma unroll
    for (int j = 0; j < 2; ++j) {
        pah[j] = __ldcg(ahrow + half * 2 + j);
        pal[j] = __ldcg(alrow + half * 2 + j);
        pwh[j] = __ldcg(whrow + half * 2 + j);
        pwl[j] = __ldcg(wlrow + half * 2 + j);
    }
    *(uint4*)(sm + sst0)         = pah[0];
    *(uint4*)(sm + sst1)         = pah[1];
    *(uint4*)(sm + 8192 + sst0)  = pal[0];
    *(uint4*)(sm + 8192 + sst1)  = pal[1];
    *(uint4*)(sm + 16384 + sst0) = pwh[0];
    *(uint4*)(sm + 16384 + sst1) = pwh[1];
    *(uint4*)(sm + 24576 + sst0) = pwl[0];
    *(uint4*)(sm + 24576 + sst1) = pwl[1];
    __syncthreads();

    for (int c = 0; c < NC; ++c) {
        const int cur = c & 1;
        const uint32_t soff = (uint32_t)cur * MST;
        if (c + 1 < NC) {
            const int ao = (c + 1) * 4 * azstep;
            const int wo = (c + 1) * 4;
#pragma unroll
            for (int j = 0; j < 2; ++j) {
                pah[j] = __ldcg(ahrow + ao + half * 2 + j);
                pal[j] = __ldcg(alrow + ao + half * 2 + j);
                pwh[j] = __ldcg(whrow + wo + half * 2 + j);
                pwl[j] = __ldcg(wlrow + wo + half * 2 + j);
            }
        }

#pragma unroll
        for (int kk = 0; kk < 2; ++kk) {
            uint32_t ah[4][4], al[4][4], bh[2][4], bl[2][4];
#pragma unroll
            for (int mi = 0; mi < 4; ++mi) {
                LDMX4(ah[mi], a_addr[mi][kk] + soff);
                LDMX4(al[mi], a_addr[mi][kk] + soff + 8192u);
            }
#pragma unroll
            for (int ng = 0; ng < 2; ++ng) {
                LDMX4(bh[ng], b_addr[ng][kk] + soff);
                LDMX4(bl[ng], b_addr[ng][kk] + soff + 8192u);
            }
#pragma unroll
            for (int mi = 0; mi < 4; ++mi) {
#pragma unroll
                for (int nf = 0; nf < 4; ++nf) {
                    const int ng = nf >> 1;
                    const int p = (nf & 1) << 1;
                    MMA_BF16(acc[mi][nf], ah[mi], bh[ng][p], bh[ng][p + 1]);
                    MMA_BF16(acc[mi][nf], ah[mi], bl[ng][p], bl[ng][p + 1]);
                    MMA_BF16(acc[mi][nf], al[mi], bh[ng][p], bh[ng][p + 1]);
                }
            }
        }

        if (c + 1 < NC) {
            char* d = sm + (cur ^ 1) * MST;
            *(uint4*)(d + sst0)         = pah[0];
            *(uint4*)(d + sst1)         = pah[1];
            *(uint4*)(d + 8192 + sst0)  = pal[0];
            *(uint4*)(d + 8192 + sst1)  = pal[1];
            *(uint4*)(d + 16384 + sst0) = pwh[0];
            *(uint4*)(d + 16384 + sst1) = pwh[1];
            *(uint4*)(d + 24576 + sst0) = pwl[0];
            *(uint4*)(d + 24576 + sst1) = pwl[1];
        }
        __syncthreads();
    }

    const int grp = lane >> 2;
    const int cl  = (lane & 3) << 1;
#pragma unroll
    for (int mi = 0; mi < 4; ++mi) {
#pragma unroll
        for (int h = 0; h < 2; ++h) {
            const int row = m0 + warp_m * 64 + mi * 16 + grp + h * 8;
            size_t coff;
            if (cmode == 0) {
                coff = (size_t)row * N;
            } else {
                int t = row >> 7, b = row & 127;
                coff = ((size_t)b * TT + t) * N;
            }
            size_t cinoff = 0;
            if (Cin) {
                int cr = ((row >> 11) << 7) + (row & 127);
                cinoff = (size_t)cr * N;
            }
#pragma unroll
            for (int nf = 0; nf < 4; ++nf) {
                const int col = n0 + warp_n * 32 + nf * 8 + cl;
                float2 v = make_float2(acc[mi][nf][h * 2], acc[mi][nf][h * 2 + 1]);
                if (bias) { v.x += bias[col]; v.y += bias[col + 1]; }
                if (Cin)  {
                    float2 ci = *(const float2*)(Cin + cinoff + col);
                    v.x += ci.x; v.y += ci.y;
                }
                if (act) { v.x = tanhf(v.x); v.y = tanhf(v.y); }
                if (C) *(float2*)(C + coff + col) = v;
                if (Chi) {
                    uint32_t hp, lp;
                    split2(v.x, v.y, hp, lp);
                    *(uint32_t*)(Chi + coff + col) = hp;
                    *(uint32_t*)(Clo + coff + col) = lp;
                }
            }
        }
    }
}

// ---------------- flag-array grid barrier (all NBLK blocks co-resident) ----------------
__device__ __forceinline__ void grid_barrier2(unsigned int gen)
{
    __syncthreads();
    __threadfence();
    if (blockIdx.x == 0) {
        if (threadIdx.x > 0 && threadIdx.x < NBLK) {
            volatile unsigned int* f = g_flags + threadIdx.x;
            while (*f != gen) { __nanosleep(32); }
        }
        __syncthreads();
        if (threadIdx.x == 0) g_go = gen;
    } else {
        if (threadIdx.x == 0) {
            *(volatile unsigned int*)(g_flags + blockIdx.x) = gen;
            while (g_go != gen) { __nanosleep(32); }
        }
        __syncthreads();
    }
    __threadfence();
}

// ---------------- persistent HMMA LSTM recurrence (256 thr; cp.async 4-stage; W pre-barrier) ----
// 128 CTAs: tile 64 rows (m0 = (bx>>6)*64) x 64 perm-cols (n0 = (bx&63)*64), K=1024.
// h kept as bf16 hi/lo; W_hh pre-split. Stage (16KB): [Ahi 4K][Alo 4K][Whi 4K][Wlo 4K];
// 4 stages. W for stages 0..2 of step t+1 is issued BEFORE the grid barrier (W is
// step-invariant); A joins after the barrier; commit groups: group c <-> chunk c.
#define RST 16384
#define RSMEM (4 * RST + 64 * 72 * 4)
__global__ __launch_bounds__(256, 1)
void lstm_rec_mma(const __nv_bfloat16* __restrict__ Whi,
                  const __nv_bfloat16* __restrict__ Wlo,
                  const float* __restrict__ gx,
                  __nv_bfloat16* __restrict__ hhi,
                  __nv_bfloat16* __restrict__ hlo,
                  int T, unsigned int gen_base)
{
    extern __shared__ char sm[];
    const uint32_t sb = smem_u32(sm);
    float* gsm = (float*)(sm + 4 * RST);
    const int tid = threadIdx.x;
    const int lane = tid & 31;
    const int wid = tid >> 5;
    const int warp_m = wid & 1;
    const int warp_n = wid >> 1;
    const int bx = blockIdx.x;
    const int m0 = (bx >> 6) << 6;          // 0 or 64
    const int n0 = (bx & 63) << 6;          // 0..4032 (perm cols)

    const int lrow = tid >> 2;
    const int quad = tid & 3;
    const uint32_t sst = (uint32_t)lrow * 64u + (uint32_t)((quad ^ (lrow & 3)) << 4);
    const uint32_t dstA = sb + sst;                  // +4096 lo
    const uint32_t dstW = sb + 8192u + sst;          // +4096 lo

    const char* whg = (const char*)(Whi + (size_t)(n0 + lrow) * 1024) + quad * 16;
    const char* wlg = (const char*)(Wlo + (size_t)(n0 + lrow) * 1024) + quad * 16;

    uint32_t a_addr[2][2], b_addr[2];
    {
        int ar = warp_m * 32 + (lane & 7) + (((lane >> 3) & 1) << 3);
        int akh = lane >> 4;
#pragma unroll
        for (int mi = 0; mi < 2; ++mi)
#pragma unroll
            for (int kk = 0; kk < 2; ++kk) {
                int row = ar + mi * 16;
                a_addr[mi][kk] = sb + (uint32_t)row * 64u
                               + (uint32_t)((((kk << 1) | akh) ^ (row & 3)) << 4);
            }
        int br = warp_n * 16 + (lane & 7) + ((lane >> 4) << 3);
        int bkh = (lane >> 3) & 1;
#pragma unroll
        for (int kk = 0; kk < 2; ++kk)
            b_addr[kk] = sb + 8192u + (uint32_t)br * 64u
                       + (uint32_t)((((kk << 1) | bkh) ^ (br & 3)) << 4);
    }

    const int grp = lane >> 2;
    const int cl  = (lane & 3) << 1;

    float cstate[4] = {0.f, 0.f, 0.f, 0.f};

    for (int t = 0; t < T; ++t) {
        // prefetch gx[t] for the cell (latency hidden under the GEMM)
        const float* gxt = gx + (size_t)t * BB * 4096;
        float4 gvr[4];
#pragma unroll
        for (int it = 0; it < 4; ++it) {
            const int idx = it * 256 + tid;
            gvr[it] = ldcg4(gxt + (size_t)(m0 + (idx >> 4)) * 4096 + n0 + (idx & 15) * 4);
        }

        float acc[2][2][4];
#pragma unroll
        for (int mi = 0; mi < 2; ++mi)
#pragma unroll
            for (int nf = 0; nf < 2; ++nf)
#pragma unroll
                for (int q = 0; q < 4; ++q) acc[mi][nf][q] = 0.f;

        if (t > 0) {
            const char* ahg = (const char*)(hhi + (size_t)(t - 1) * BB * 1024
                                            + (size_t)(m0 + lrow) * 1024) + quad * 16;
            const char* alg = (const char*)(hlo + (size_t)(t - 1) * BB * 1024
                                            + (size_t)(m0 + lrow) * 1024) + quad * 16;

            // A prologue: chunks 0..2 (W for these stages was issued before the barrier)
#pragma unroll
            for (int s = 0; s < 3; ++s) {
                CP_ASYNC16(dstA + (uint32_t)s * RST,          ahg + s * 64);
                CP_ASYNC16(dstA + 4096u + (uint32_t)s * RST,  alg + s * 64);
                CP_COMMIT();
            }

            for (int c = 0; c < 32; ++c) {
                if (c <= 29) CP_WAIT(2);
                else if (c == 30) CP_WAIT(1);
                else CP_WAIT(0);
                __syncthreads();

                if (c + 3 < 32) {
                    const uint32_t so = (uint32_t)((c + 3) & 3) * RST;
                    CP_ASYNC16(dstA + so,          ahg + (c + 3) * 64);
                    CP_ASYNC16(dstA + 4096u + so,  alg + (c + 3) * 64);
                    CP_ASYNC16(dstW + so,          whg + (c + 3) * 64);
                    CP_ASYNC16(dstW + 4096u + so,  wlg + (c + 3) * 64);
                    CP_COMMIT();
                }

                const uint32_t soff = (uint32_t)(c & 3) * RST;
#pragma unroll
                for (int kk = 0; kk < 2; ++kk) {
                    uint32_t ah[2][4], al[2][4], bh[4], bl[4];
                    LDMX4(ah[0], a_addr[0][kk] + soff);
                    LDMX4(ah[1], a_addr[1][kk] + soff);
                    LDMX4(al[0], a_addr[0][kk] + soff + 4096u);
                    LDMX4(al[1], a_addr[1][kk] + soff + 4096u);
                    LDMX4(bh, b_addr[kk] + soff);
                    LDMX4(bl, b_addr[kk] + soff + 4096u);
#pragma unroll
                    for (int mi = 0; mi < 2; ++mi) {
#pragma unroll
                        for (int nf = 0; nf < 2; ++nf) {
                            const int p = nf << 1;
                            MMA_BF16(acc[mi][nf], ah[mi], bh[p], bh[p + 1]);
                            MMA_BF16(acc[mi][nf], ah[mi], bl[p], bl[p + 1]);
                            MMA_BF16(acc[mi][nf], al[mi], bh[p], bh[p + 1]);
                        }
                    }
                }
            }
            __syncthreads();
        }

        // gate fragments -> smem (64 x 72 fp32)
#pragma unroll
        for (int mi = 0; mi < 2; ++mi)
#pragma unroll
            for (int h2 = 0; h2 < 2; ++h2) {
                const int row = warp_m * 32 + mi * 16 + grp + h2 * 8;
#pragma unroll
                for (int nf = 0; nf < 2; ++nf) {
                    const int col = warp_n * 16 + nf * 8 + cl;
                    gsm[row * 72 + col]     = acc[mi][nf][h2 * 2];
                    gsm[row * 72 + col + 1] = acc[mi][nf][h2 * 2 + 1];
                }
            }
        __syncthreads();

        // fused cell: gates = gsm + gx[t] (prefetched); c in regs; write h {hi, lo}
#pragma unroll
        for (int it = 0; it < 4; ++it) {
            const int idx = it * 256 + tid;
            const int crow = idx >> 4;
            const int cj = idx & 15;
            const int rg = m0 + crow;
            const int jg = (n0 >> 2) + cj;
            float4 ga = *(const float4*)(gsm + crow * 72 + cj * 4);
            float4 gv = gvr[it];
            float gi = sigm(ga.x + gv.x);
            float gf = sigm(ga.y + gv.y);
            float gg = tanhf(ga.z + gv.z);
            float go = sigm(ga.w + gv.w);
            float cc = gf * cstate[it] + gi * gg;
            cstate[it] = cc;
            float hv = go * tanhf(cc);
            const size_t off = (size_t)t * BB * 1024 + (size_t)rg * 1024 + jg;
            __nv_bfloat16 hh = __float2bfloat16(hv);
            hhi[off] = hh;
            hlo[off] = __float2bfloat16(hv - __bfloat162float(hh));
        }

        // W prefetch for next step's stages 0..2 (uncommitted; joins group 0 after barrier)
        if (t + 1 < T) {
#pragma unroll
            for (int s = 0; s < 3; ++s) {
                CP_ASYNC16(dstW + (uint32_t)s * RST,          whg + s * 64);
                CP_ASYNC16(dstW + 4096u + (uint32_t)s * RST,  wlg + s * 64);
            }
        }

        grid_barrier2(gen_base + (unsigned int)t);
    }
}

// ---------------- one-time convert: fp32 row-major -> bf16 hi/lo ----------------
__global__ void convert_w(const float* __restrict__ in,
                          __nv_bfloat16* __restrict__ hi, __nv_bfloat16* __restrict__ lo,
                          int ldk, int K, int doperm, int k0)
{
    int ro = blockIdx.x;
    int sr = doperm ? ((ro & 3) * 1024 + (ro >> 2)) : ro;
    const float* s = in + (size_t)sr * ldk + k0;
    for (int k = threadIdx.x * 4; k < K; k += blockDim.x * 4) {
        float4 v = __ldcg((const float4*)(s + k));
        uint32_t hp0, lp0, hp1, lp1;
        split2(v.x, v.y, hp0, lp0);
        split2(v.z, v.w, hp1, lp1);
        *(uint2*)(hi + (size_t)ro * K + k) = make_uint2(hp0, hp1);
        *(uint2*)(lo + (size_t)ro * K + k) = make_uint2(lp0, lp1);
    }
}

// all three gate-permuted bias sums in one launch (i in [0, 12288))
__global__ void addperm3(const float* a0, const float* b0,
                         const float* a1, const float* b1,
                         const float* a2, const float* b2,
                         float* __restrict__ o)
{
    int i = blockIdx.x * blockDim.x + threadIdx.x;
    int sec = i >> 12;
    int li = i & 4095;
    int j = li >> 2, g = li & 3;
    int s = g * 1024 + j;
    const float* a = sec == 0 ? a0 : (sec == 1 ? a1 : a2);
    const float* b = sec == 0 ? b0 : (sec == 1 ? b1 : b2);
    o[i] = a[s] + b[s];
}

// ---------------- host ----------------
extern "C" void kernel_launch(void* const* d_in, const int* in_sizes, int n_in,
                              void* d_out, int out_size)
{
    const float* z      = (const float*)d_in[0];
    const float* x      = (const float*)d_in[1];
    const float* fcz_w  = (const float*)d_in[2];
    const float* fcz_b  = (const float*)d_in[3];
    const float* c_wih  = (const float*)d_in[4];
    const float* c_whh  = (const float*)d_in[5];
    const float* c_bih  = (const float*)d_in[6];
    const float* c_bhh  = (const float*)d_in[7];
    const float* fcc_w  = (const float*)d_in[8];
    const float* fcc_b  = (const float*)d_in[9];
    const float* d0_wih = (const float*)d_in[10];
    const float* d0_whh = (const float*)d_in[11];
    const float* d0_bih = (const float*)d_in[12];
    const float* d0_bhh = (const float*)d_in[13];
    const float* d1_wih = (const float*)d_in[14];
    const float* d1_whh = (const float*)d_in[15];
    const float* d1_bih = (const float*)d_in[16];
    const float* d1_bhh = (const float*)d_in[17];
    const float* out_w  = (const float*)d_in[18];
    const float* out_b  = (const float*)d_in[19];
    float* out = (float*)d_out;

    float *gxc, *gxe, *gx, *bsum_p;
    __nv_bfloat16 *hhi, *hlo, *zhi, *zlo, *xhi, *xlo, *cinhi, *cinlo, *embhi, *emblo;
    __nv_bfloat16 *fczw_hi, *fczw_lo, *fccw_hi, *fccw_lo;
    __nv_bfloat16 *cwih_hi, *cwih_lo, *cwhh_hi, *cwhh_lo;
    __nv_bfloat16 *d0wih_hi, *d0wih_lo, *d0wihE_hi, *d0wihE_lo, *d0whh_hi, *d0whh_lo;
    __nv_bfloat16 *d1wih_hi, *d1wih_lo, *d1whh_hi, *d1whh_lo, *outw_hi, *outw_lo;
    cudaGetSymbolAddress((void**)&gxc,       g_gxc);
    cudaGetSymbolAddress((void**)&gxe,       g_gxe);
    cudaGetSymbolAddress((void**)&gx,        g_gx);
    cudaGetSymbolAddress((void**)&bsum_p,    g_bsum_p);
    cudaGetSymbolAddress((void**)&hhi,       g_hhi);
    cudaGetSymbolAddress((void**)&hlo,       g_hlo);
    cudaGetSymbolAddress((void**)&zhi,       g_zhi);
    cudaGetSymbolAddress((void**)&zlo,       g_zlo);
    cudaGetSymbolAddress((void**)&xhi,       g_xhi);
    cudaGetSymbolAddress((void**)&xlo,       g_xlo);
    cudaGetSymbolAddress((void**)&cinhi,     g_cinhi);
    cudaGetSymbolAddress((void**)&cinlo,     g_cinlo);
    cudaGetSymbolAddress((void**)&embhi,     g_embhi);
    cudaGetSymbolAddress((void**)&emblo,     g_emblo);
    cudaGetSymbolAddress((void**)&fczw_hi,   g_fczw_hi);
    cudaGetSymbolAddress((void**)&fczw_lo,   g_fczw_lo);
    cudaGetSymbolAddress((void**)&fccw_hi,   g_fccw_hi);
    cudaGetSymbolAddress((void**)&fccw_lo,   g_fccw_lo);
    cudaGetSymbolAddress((void**)&cwih_hi,   g_cwih_hi);
    cudaGetSymbolAddress((void**)&cwih_lo,   g_cwih_lo);
    cudaGetSymbolAddress((void**)&cwhh_hi,   g_cwhh_hi);
    cudaGetSymbolAddress((void**)&cwhh_lo,   g_cwhh_lo);
    cudaGetSymbolAddress((void**)&d0wih_hi,  g_d0wih_hi);
    cudaGetSymbolAddress((void**)&d0wih_lo,  g_d0wih_lo);
    cudaGetSymbolAddress((void**)&d0wihE_hi, g_d0wihE_hi);
    cudaGetSymbolAddress((void**)&d0wihE_lo, g_d0wihE_lo);
    cudaGetSymbolAddress((void**)&d0whh_hi,  g_d0whh_hi);
    cudaGetSymbolAddress((void**)&d0whh_lo,  g_d0whh_lo);
    cudaGetSymbolAddress((void**)&d1wih_hi,  g_d1wih_hi);
    cudaGetSymbolAddress((void**)&d1wih_lo,  g_d1wih_lo);
    cudaGetSymbolAddress((void**)&d1whh_hi,  g_d1whh_hi);
    cudaGetSymbolAddress((void**)&d1whh_lo,  g_d1whh_lo);
    cudaGetSymbolAddress((void**)&outw_hi,   g_outw_hi);
    cudaGetSymbolAddress((void**)&outw_lo,   g_outw_lo);

    cudaFuncSetAttribute(gemm_mma, cudaFuncAttributeMaxDynamicSharedMemorySize, 2 * MST);
    cudaFuncSetAttribute(lstm_rec_mma, cudaFuncAttributeMaxDynamicSharedMemorySize, RSMEM);

    dim3 blk(256);
    const __nv_bfloat16* nbf = nullptr;

    // ---- one-time converts ----
    convert_w<<<2048, 128>>>(z, zhi, zlo, ZZ, ZZ, 0, 0);
    convert_w<<<1024, 128>>>(fcz_w, fczw_hi, fczw_lo, ZZ, ZZ, 0, 0);
    convert_w<<<4096, 256>>>(c_wih, cwih_hi, cwih_lo, HC, HC, 1, 0);
    convert_w<<<4096, 256>>>(c_whh, cwhh_hi, cwhh_lo, HC, HC, 1, 0);
    addperm3<<<48, 256>>>(c_bih, c_bhh, d0_bih, d0_bhh, d1_bih, d1_bhh, bsum_p);

    // ---- conductor ----
    // cin (hi/lo only): z-gather x fcz_w
    gemm_mma<<<dim3(HC / 128, (SSEQ * BB) / 128), blk, 2 * MST>>>(
        zhi, zlo, fczw_hi, fczw_lo, fcz_b, nullptr, nullptr, cinhi, cinlo,
        ZZ, HC, 1, 0, 0);
    gemm_mma<<<dim3(4 * HC / 128, (SSEQ * BB) / 128), blk, 2 * MST>>>(
        cinhi, cinlo, cwih_hi, cwih_lo, bsum_p, nullptr, gxc, nullptr, nullptr,
        HC, 4 * HC, 0, 0, 0);
    lstm_rec_mma<<<NBLK, blk, RSMEM>>>(cwhh_hi, cwhh_lo, gxc, hhi, hlo, SSEQ, 1u);

    convert_w<<<512, 256>>>(fcc_w, fccw_hi, fccw_lo, HC, HC, 0, 0);
    // emb = tanh(condh x fcc_w + b), split outputs
    gemm_mma<<<dim3(EE / 128, (SSEQ * BB) / 128), blk, 2 * MST>>>(
        hhi, hlo, fccw_hi, fccw_lo, fcc_b, nullptr, nullptr, embhi, emblo,
        HC, EE, 0, 0, 1);
    convert_w<<<4096, 256>>>(d0_wih, d0wihE_hi, d0wihE_lo, VV + EE, EE, 1, VV);
    gemm_mma<<<dim3(4 * HD / 128, (SSEQ * BB) / 128), blk, 2 * MST>>>(
        embhi, emblo, d0wihE_hi, d0wihE_lo, bsum_p + 4096, nullptr, gxe, nullptr, nullptr,
        EE, 4 * HD, 0, 0, 0);

    // ---- decoder layer 0 ----
    convert_w<<<32768, 128>>>(x, xhi, xlo, VV, VV, 0, 0);
    convert_w<<<4096, 256>>>(d0_wih, d0wih_hi, d0wih_lo, VV + EE, VV, 1, 0);
    gemm_mma<<<dim3(4 * HD / 128, (TT * BB) / 128), blk, 2 * MST>>>(
        xhi, xlo, d0wih_hi, d0wih_lo, nullptr, gxe, gx, nullptr, nullptr,
        VV, 4 * HD, 2, 0, 0);
    convert_w<<<4096, 256>>>(d0_whh, d0whh_hi, d0whh_lo, HD, HD, 1, 0);
    lstm_rec_mma<<<NBLK, blk, RSMEM>>>(d0whh_hi, d0whh_lo, gx, hhi, hlo, TT, 17u);

    // ---- decoder layer 1 ----
    convert_w<<<4096, 256>>>(d1_wih, d1wih_hi, d1wih_lo, HD, HD, 1, 0);
    gemm_mma<<<dim3(4 * HD / 128, (TT * BB) / 128), blk, 2 * MST>>>(
        hhi, hlo, d1wih_hi, d1wih_lo, bsum_p + 8192, nullptr, gx, nullptr, nullptr,
        HD, 4 * HD, 0, 0, 0);
    convert_w<<<4096, 256>>>(d1_whh, d1whh_hi, d1whh_lo, HD, HD, 1, 0);
    lstm_rec_mma<<<NBLK, blk, RSMEM>>>(d1whh_hi, d1whh_lo, gx, hhi, hlo, TT, 273u);

    // ---- output projection (time-major -> [B,T,V]) ----
    convert_w<<<1024, 256>>>(out_w, outw_hi, outw_lo, HD, HD, 0, 0);
    gemm_mma<<<dim3(VV / 128, (TT * BB) / 128), blk, 2 * MST>>>(
        hhi, hlo, outw_hi, outw_lo, out_b, nullptr, out, nullptr, nullptr,
        HD, VV, 0, 1, 0);

    (void)nbf;
}

// round 14
// speedup vs baseline: 1.1223x; 1.1223x over previous
#include <cuda_runtime.h>
#include <cuda_bf16.h>
#include <cstdint>

#define BB 128
#define SSEQ 16
#define TT 256
#define ZZ 512
#define HC 1024
#define EE 512
#define HD 1024
#define VV 1024
#define NBLK 128

// ---------------- scratch (device globals; zero-init at module load) ----------------
__device__ float g_zero[BB * HD];                       // never written: stays zero
__device__ float g_cin[SSEQ * BB * HC];
__device__ float g_gxc[SSEQ * BB * 4 * HC];             // perm gate order
__device__ float g_condh[SSEQ * BB * HC];
__device__ float g_emb[SSEQ * BB * EE];
__device__ float g_gxe[SSEQ * BB * 4 * HD];             // perm
__device__ float g_gx[TT * BB * 4 * HD];                // perm
__device__ float g_h0[TT * BB * HD];
__device__ float g_h1[TT * BB * HD];
__device__ float g_bsum_p[3 * 4 * HD];
// bf16 h history (hi/lo split), shared across the three recurrences (serial launches)
__device__ __align__(16) __nv_bfloat16 g_hhi[TT * BB * HD];
__device__ __align__(16) __nv_bfloat16 g_hlo[TT * BB * HD];
// bf16 hi/lo split weights (mma consumers)
__device__ __align__(16) __nv_bfloat16 g_cwih_hi[4 * HC * HC];
__device__ __align__(16) __nv_bfloat16 g_cwih_lo[4 * HC * HC];
__device__ __align__(16) __nv_bfloat16 g_cwhh_hi[4 * HC * HC];
__device__ __align__(16) __nv_bfloat16 g_cwhh_lo[4 * HC * HC];
__device__ __align__(16) __nv_bfloat16 g_d0wih_hi[4 * HD * VV];
__device__ __align__(16) __nv_bfloat16 g_d0wih_lo[4 * HD * VV];
__device__ __align__(16) __nv_bfloat16 g_d0wihE_hi[4 * HD * EE];
__device__ __align__(16) __nv_bfloat16 g_d0wihE_lo[4 * HD * EE];
__device__ __align__(16) __nv_bfloat16 g_d0whh_hi[4 * HD * HD];
__device__ __align__(16) __nv_bfloat16 g_d0whh_lo[4 * HD * HD];
__device__ __align__(16) __nv_bfloat16 g_d1wih_hi[4 * HD * HD];
__device__ __align__(16) __nv_bfloat16 g_d1wih_lo[4 * HD * HD];
__device__ __align__(16) __nv_bfloat16 g_d1whh_hi[4 * HD * HD];
__device__ __align__(16) __nv_bfloat16 g_d1whh_lo[4 * HD * HD];
__device__ __align__(16) __nv_bfloat16 g_outw_hi[VV * HD];
__device__ __align__(16) __nv_bfloat16 g_outw_lo[VV * HD];

// grid-barrier state (monotonic generation; count self-resets)
__device__ volatile unsigned int g_bar_gen;
__device__ unsigned int g_bar_cnt;

// ---------------- helpers ----------------
__device__ __forceinline__ float4 ldcg4(const float* p) {
    return __ldcg((const float4*)(p));
}
__device__ __forceinline__ float sigm(float x) { return 1.f / (1.f + expf(-x)); }

__device__ __forceinline__ uint32_t smem_u32(const void* p) {
    uint32_t a;
    asm("{ .reg .u64 t; cvta.to.shared.u64 t, %1; cvt.u32.u64 %0, t; }" : "=r"(a) : "l"(p));
    return a;
}
__device__ __forceinline__ uint32_t pack_bf16(__nv_bfloat16 a, __nv_bfloat16 b) {
    return (uint32_t)__bfloat16_as_ushort(a) | ((uint32_t)__bfloat16_as_ushort(b) << 16);
}
__device__ __forceinline__ void split2(float x, float y, uint32_t& hp, uint32_t& lp) {
    __nv_bfloat16 hx = __float2bfloat16(x), hy = __float2bfloat16(y);
    __nv_bfloat16 lx = __float2bfloat16(x - __bfloat162float(hx));
    __nv_bfloat16 ly = __float2bfloat16(y - __bfloat162float(hy));
    hp = pack_bf16(hx, hy);
    lp = pack_bf16(lx, ly);
}
// packed fp32x2 helpers (FFMA2 path, small GEMMs)
__device__ __forceinline__ unsigned long long ffma2(unsigned long long a,
                                                    unsigned long long b,
                                                    unsigned long long c) {
    unsigned long long d;
    asm("fma.rn.f32x2 %0, %1, %2, %3;" : "=l"(d) : "l"(a), "l"(b), "l"(c));
    return d;
}
__device__ __forceinline__ unsigned long long pk2(float x, float y) {
    unsigned long long r;
    asm("mov.b64 %0, {%1, %2};" : "=l"(r) : "f"(x), "f"(y));
    return r;
}
__device__ __forceinline__ float2 upk2(unsigned long long v) {
    float2 d;
    asm("mov.b64 {%0, %1}, %2;" : "=f"(d.x), "=f"(d.y) : "l"(v));
    return d;
}

// ---------------- mma.sync (HMMA) + cp.async primitives — baseline PTX ----------------
#define MMA_BF16(d, a, b0, b1)                                                  \
    asm volatile("mma.sync.aligned.m16n8k16.row.col.f32.bf16.bf16.f32 "         \
        "{%0,%1,%2,%3}, {%4,%5,%6,%7}, {%8,%9}, {%0,%1,%2,%3};"                 \
        : "+f"((d)[0]), "+f"((d)[1]), "+f"((d)[2]), "+f"((d)[3])                \
        : "r"((a)[0]), "r"((a)[1]), "r"((a)[2]), "r"((a)[3]), "r"(b0), "r"(b1))

#define LDMX4(r, addr)                                                          \
    asm volatile("ldmatrix.sync.aligned.m8n8.x4.shared.b16 {%0,%1,%2,%3}, [%4];" \
        : "=r"((r)[0]), "=r"((r)[1]), "=r"((r)[2]), "=r"((r)[3]) : "r"(addr))

#define CP_ASYNC16(dst, src) \
    asm volatile("cp.async.cg.shared.global [%0], [%1], 16;" :: "r"(dst), "l"(src))
#define CP_COMMIT() asm volatile("cp.async.commit_group;" ::: "memory")
#define CP_WAIT(n)  asm volatile("cp.async.wait_group %0;" :: "n"(n) : "memory")

// ---------------- HMMA GEMM (R11 version): C = gather(A)[M,K] * W[N,K]^T (+bias)(+Cin) ------
// A fp32 split to bf16 hi/lo in transit; W pre-split. 128x128 tile, 8 warps, K-chunk 32.
// amode: 0 = A row m; 2 = prev-x gather. Cin: row (t>>4)*BB+b. cmode: 0 = row m; 1 = row (b*TT+t).
#define MST 32768
__global__ __launch_bounds__(256, 1)
void gemm_mma(const float* __restrict__ A,
              const __nv_bfloat16* __restrict__ Whi,
              const __nv_bfloat16* __restrict__ Wlo,
              const float* __restrict__ bias, const float* __restrict__ Cin,
              float* __restrict__ C,
              int K, int N, int amode, int cmode)
{
    extern __shared__ char sm[];
    const uint32_t sb = smem_u32(sm);
    const int tid = threadIdx.x;
    const int lane = tid & 31;
    const int wid = tid >> 5;
    const int warp_m = wid & 1;
    const int warp_n = wid >> 1;
    const int m0 = blockIdx.y << 7;
    const int n0 = blockIdx.x << 7;

    const int lrow = tid >> 1;
    const int half = tid & 1;

    const float* arow;
    {
        int m = m0 + lrow;
        if (amode == 0) {
            arow = A + (size_t)m * K;
        } else {
            int t = m >> 7, b = m & 127;
            arow = (t == 0) ? g_zero : A + ((size_t)b * TT + (t - 1)) * 1024;
        }
    }
    const uint4* whrow = (const uint4*)(Whi + (size_t)(n0 + lrow) * K);
    const uint4* wlrow = (const uint4*)(Wlo + (size_t)(n0 + lrow) * K);

    const uint32_t sst0 = (uint32_t)lrow * 64u + (uint32_t)(((half * 2)     ^ (lrow & 3)) << 4);
    const uint32_t sst1 = (uint32_t)lrow * 64u + (uint32_t)(((half * 2 + 1) ^ (lrow & 3)) << 4);

    uint32_t a_addr[4][2], b_addr[2][2];
    {
        int ar = warp_m * 64 + (lane & 7) + (((lane >> 3) & 1) << 3);
        int akh = lane >> 4;
        int br = warp_n * 32 + (lane & 7) + ((lane >> 4) << 3);
        int bkh = (lane >> 3) & 1;
#pragma unroll
        for (int mi = 0; mi < 4; ++mi)
#pragma unroll
            for (int kk = 0; kk < 2; ++kk) {
                int row = ar + mi * 16;
                a_addr[mi][kk] = sb + (uint32_t)row * 64u
                               + (uint32_t)((((kk << 1) | akh) ^ (row & 3)) << 4);
            }
#pragma unroll
        for (int ng = 0; ng < 2; ++ng)
#pragma unroll
            for (int kk = 0; kk < 2; ++kk) {
                int row = br + ng * 16;
                b_addr[ng][kk] = sb + 16384u + (uint32_t)row * 64u
                               + (uint32_t)((((kk << 1) | bkh) ^ (row & 3)) << 4);
            }
    }

    float acc[4][4][4];
#pragma unroll
    for (int mi = 0; mi < 4; ++mi)
#pragma unroll
        for (int nf = 0; nf < 4; ++nf)
#pragma unroll
            for (int q = 0; q < 4; ++q) acc[mi][nf][q] = 0.f;

    const int NC = K >> 5;
    float4 pa[4];
    uint4 pwh[2], pwl[2];

#pragma unroll
    for (int i = 0; i < 4; ++i) pa[i] = ldcg4(arow + half * 16 + i * 4);
#pragma unroll
    for (int j = 0; j < 2; ++j) {
        pwh[j] = __ldcg(whrow + half * 2 + j);
        pwl[j] = __ldcg(wlrow + half * 2 + j);
    }
    {
        uint32_t h0a, l0a, h0b, l0b, h1a, l1a, h1b, l1b;
        split2(pa[0].x, pa[0].y, h0a, l0a); split2(pa[0].z, pa[0].w, h0b, l0b);
        split2(pa[1].x, pa[1].y, h1a, l1a); split2(pa[1].z, pa[1].w, h1b, l1b);
        *(uint4*)(sm + sst0)         = make_uint4(h0a, h0b, h1a, h1b);
        *(uint4*)(sm + 8192 + sst0)  = make_uint4(l0a, l0b, l1a, l1b);
        split2(pa[2].x, pa[2].y, h0a, l0a); split2(pa[2].z, pa[2].w, h0b, l0b);
        split2(pa[3].x, pa[3].y, h1a, l1a); split2(pa[3].z, pa[3].w, h1b, l1b);
        *(uint4*)(sm + sst1)         = make_uint4(h0a, h0b, h1a, h1b);
        *(uint4*)(sm + 8192 + sst1)  = make_uint4(l0a, l0b, l1a, l1b);
        *(uint4*)(sm + 16384 + sst0) = pwh[0];
        *(uint4*)(sm + 16384 + sst1) = pwh[1];
        *(uint4*)(sm + 24576 + sst0) = pwl[0];
        *(uint4*)(sm + 24576 + sst1) = pwl[1];
    }
    __syncthreads();

    for (int c = 0; c < NC; ++c) {
        const int cur = c & 1;
        const uint32_t soff = (uint32_t)cur * MST;
        if (c + 1 < NC) {
#pragma unroll
            for (int i = 0; i < 4; ++i)
                pa[i] = ldcg4(arow + (c + 1) * 32 + half * 16 + i * 4);
#pragma unroll
            for (int j = 0; j < 2; ++j) {
                pwh[j] = __ldcg(whrow + (c + 1) * 4 + half * 2 + j);
                pwl[j] = __ldcg(wlrow + (c + 1) * 4 + half * 2 + j);
            }
        }

#pragma unroll
        for (int kk = 0; kk < 2; ++kk) {
            uint32_t ah[4][4], al[4][4], bh[2][4], bl[2][4];
#pragma unroll
            for (int mi = 0; mi < 4; ++mi) {
                LDMX4(ah[mi], a_addr[mi][kk] + soff);
                LDMX4(al[mi], a_addr[mi][kk] + soff + 8192u);
            }
#pragma unroll
            for (int ng = 0; ng < 2; ++ng) {
                LDMX4(bh[ng], b_addr[ng][kk] + soff);
                LDMX4(bl[ng], b_addr[ng][kk] + soff + 8192u);
            }
#pragma unroll
            for (int mi = 0; mi < 4; ++mi) {
#pragma unroll
                for (int nf = 0; nf < 4; ++nf) {
                    const int ng = nf >> 1;
                    const int p = (nf & 1) << 1;
                    MMA_BF16(acc[mi][nf], ah[mi], bh[ng][p], bh[ng][p + 1]);
                    MMA_BF16(acc[mi][nf], ah[mi], bl[ng][p], bl[ng][p + 1]);
                    MMA_BF16(acc[mi][nf], al[mi], bh[ng][p], bh[ng][p + 1]);
                }
            }
        }

        if (c + 1 < NC) {
            char* d = sm + (cur ^ 1) * MST;
            uint32_t h0a, l0a, h0b, l0b, h1a, l1a, h1b, l1b;
            split2(pa[0].x, pa[0].y, h0a, l0a); split2(pa[0].z, pa[0].w, h0b, l0b);
            split2(pa[1].x, pa[1].y, h1a, l1a); split2(pa[1].z, pa[1].w, h1b, l1b);
            *(uint4*)(d + sst0)         = make_uint4(h0a, h0b, h1a, h1b);
            *(uint4*)(d + 8192 + sst0)  = make_uint4(l0a, l0b, l1a, l1b);
            split2(pa[2].x, pa[2].y, h0a, l0a); split2(pa[2].z, pa[2].w, h0b, l0b);
            split2(pa[3].x, pa[3].y, h1a, l1a); split2(pa[3].z, pa[3].w, h1b, l1b);
            *(uint4*)(d + sst1)         = make_uint4(h0a, h0b, h1a, h1b);
            *(uint4*)(d + 8192 + sst1)  = make_uint4(l0a, l0b, l1a, l1b);
            *(uint4*)(d + 16384 + sst0) = pwh[0];
            *(uint4*)(d + 16384 + sst1) = pwh[1];
            *(uint4*)(d + 24576 + sst0) = pwl[0];
            *(uint4*)(d + 24576 + sst1) = pwl[1];
        }
        __syncthreads();
    }

    const int grp = lane >> 2;
    const int cl  = (lane & 3) << 1;
#pragma unroll
    for (int mi = 0; mi < 4; ++mi) {
#pragma unroll
        for (int h = 0; h < 2; ++h) {
            const int row = m0 + warp_m * 64 + mi * 16 + grp + h * 8;
            size_t coff;
            if (cmode == 0) {
                coff = (size_t)row * N;
            } else {
                int t = row >> 7, b = row & 127;
                coff = ((size_t)b * TT + t) * N;
            }
            size_t cinoff = 0;
            if (Cin) {
                int cr = ((row >> 11) << 7) + (row & 127);
                cinoff = (size_t)cr * N;
            }
#pragma unroll
            for (int nf = 0; nf < 4; ++nf) {
                const int col = n0 + warp_n * 32 + nf * 8 + cl;
                float2 v = make_float2(acc[mi][nf][h * 2], acc[mi][nf][h * 2 + 1]);
                if (bias) { v.x += bias[col]; v.y += bias[col + 1]; }
                if (Cin)  {
                    float2 ci = *(const float2*)(Cin + cinoff + col);
                    v.x += ci.x; v.y += ci.y;
                }
                *(float2*)(C + coff + col) = v;
            }
        }
    }
}

// ---------------- grid barrier (atomic counter; all NBLK blocks co-resident) ----------------
__device__ __forceinline__ void grid_barrier()
{
    __syncthreads();
    __threadfence();
    if (threadIdx.x == 0) {
        unsigned int gen = g_bar_gen;
        if (atomicAdd(&g_bar_cnt, 1u) == NBLK - 1u) {
            g_bar_cnt = 0u;
            __threadfence();
            g_bar_gen = gen + 1u;
        } else {
            while (g_bar_gen == gen) { __nanosleep(64); }
        }
    }
    __syncthreads();
}

// ---------------- persistent HMMA LSTM recurrence (R11 + persistent Whi in smem) ----------
// 128 CTAs: tile 64 rows (m0 = (bx>>6)*64) x 64 perm-cols (n0 = (bx&63)*64), K=1024.
// Whi slice (64 rows x 2048B) persisted in smem across all T steps (loaded once,
// ^(row&7) 16B-chunk swizzle on 2048B rows -> conflict-free for 8-row ldmatrix groups).
// Streamed per chunk via 4-stage cp.async: [Ahi 4K][Alo 4K][Wlo 4K] = 12KB stages.
#define RST 12288
#define RGOFF (4 * RST)                      // gates: 64 x 72 fp32
#define RWHI (RGOFF + 64 * 72 * 4)           // persistent Whi: 64 x 2048B
#define RSMEM (RWHI + 64 * 2048)             // 198656 B
__global__ __launch_bounds__(256, 1)
void lstm_rec_mma(const __nv_bfloat16* __restrict__ Whi,
                  const __nv_bfloat16* __restrict__ Wlo,
                  const float* __restrict__ gx,
                  float* __restrict__ hf,
                  __nv_bfloat16* __restrict__ hhi,
                  __nv_bfloat16* __restrict__ hlo,
                  int T)
{
    extern __shared__ char sm[];
    const uint32_t sb = smem_u32(sm);
    float* gsm = (float*)(sm + RGOFF);
    const int tid = threadIdx.x;
    const int lane = tid & 31;
    const int wid = tid >> 5;
    const int warp_m = wid & 1;
    const int warp_n = wid >> 1;
    const int bx = blockIdx.x;
    const int m0 = (bx >> 6) << 6;          // 0 or 64
    const int n0 = (bx & 63) << 6;          // 0..4032 (perm cols)

    // loader: thread -> (row 0..63, 16B quad 0..3); stage swizzle chunk ^= row&3
    const int lrow = tid >> 2;
    const int quad = tid & 3;
    const uint32_t sst = (uint32_t)lrow * 64u + (uint32_t)((quad ^ (lrow & 3)) << 4);
    const uint32_t dstAh = sb + sst;
    const uint32_t dstAl = sb + 4096u + sst;
    const uint32_t dstWl = sb + 8192u + sst;

    const char* wlg = (const char*)(Wlo + (size_t)(n0 + lrow) * 1024) + quad * 16;

    // one-time: persist Whi slice into smem (64 rows x 128 16B-units, ^(r&7) swizzle)
    for (int i = tid; i < 64 * 128; i += 256) {
        int r = i >> 7, c16 = i & 127;
        uint4 v = __ldcg((const uint4*)(Whi + (size_t)(n0 + r) * 1024) + c16);
        *(uint4*)(sm + RWHI + r * 2048 + ((c16 ^ (r & 7)) << 4)) = v;
    }

    // ldmatrix addresses. A (staged): base 0 (hi) / +4096 (lo). Wlo (staged): base +8192.
    // Whi (persistent): per-chunk address from rowbase/rowx/kbase.
    uint32_t a_addr[2][2], bl_addr[2];
    uint32_t bh_rowbase, bh_rowx, bh_k[2];
    {
        int ar = warp_m * 32 + (lane & 7) + (((lane >> 3) & 1) << 3);
        int akh = lane >> 4;
#pragma unroll
        for (int mi = 0; mi < 2; ++mi)
#pragma unroll
            for (int kk = 0; kk < 2; ++kk) {
                int row = ar + mi * 16;
                a_addr[mi][kk] = sb + (uint32_t)row * 64u
                               + (uint32_t)((((kk << 1) | akh) ^ (row & 3)) << 4);
            }
        int br = warp_n * 16 + (lane & 7) + ((lane >> 4) << 3);
        int bkh = (lane >> 3) & 1;
#pragma unroll
        for (int kk = 0; kk < 2; ++kk)
            bl_addr[kk] = sb + 8192u + (uint32_t)br * 64u
                        + (uint32_t)((((kk << 1) | bkh) ^ (br & 3)) << 4);
        bh_rowbase = sb + RWHI + (uint32_t)br * 2048u;
        bh_rowx = (uint32_t)(br & 7);
        bh_k[0] = (uint32_t)bkh;             // col16 = c*4 + kk*2 + bkh
        bh_k[1] = (uint32_t)(2 + bkh);
    }
    __syncthreads();   // Whi persisted & visible

    const int grp = lane >> 2;
    const int cl  = (lane & 3) << 1;

    float cstate[4] = {0.f, 0.f, 0.f, 0.f};

    for (int t = 0; t < T; ++t) {
        // prefetch gx[t] for the cell (latency hidden under the GEMM)
        const float* gxt = gx + (size_t)t * BB * 4096;
        float4 gvr[4];
#pragma unroll
        for (int it = 0; it < 4; ++it) {
            const int idx = it * 256 + tid;
            gvr[it] = ldcg4(gxt + (size_t)(m0 + (idx >> 4)) * 4096 + n0 + (idx & 15) * 4);
        }

        float acc[2][2][4];
#pragma unroll
        for (int mi = 0; mi < 2; ++mi)
#pragma unroll
            for (int nf = 0; nf < 2; ++nf)
#pragma unroll
                for (int q = 0; q < 4; ++q) acc[mi][nf][q] = 0.f;

        if (t > 0) {
            const char* ahg = (const char*)(hhi + (size_t)(t - 1) * BB * 1024
                                            + (size_t)(m0 + lrow) * 1024) + quad * 16;
            const char* alg = (const char*)(hlo + (size_t)(t - 1) * BB * 1024
                                            + (size_t)(m0 + lrow) * 1024) + quad * 16;

            // prologue: chunks 0..2 into stages 0..2
#pragma unroll
            for (int s = 0; s < 3; ++s) {
                const uint32_t so = (uint32_t)s * RST;
                CP_ASYNC16(dstAh + so, ahg + s * 64);
                CP_ASYNC16(dstAl + so, alg + s * 64);
                CP_ASYNC16(dstWl + so, wlg + s * 64);
                CP_COMMIT();
            }

            for (int c = 0; c < 32; ++c) {
                if (c <= 29) CP_WAIT(2);
                else if (c == 30) CP_WAIT(1);
                else CP_WAIT(0);
                __syncthreads();

                if (c + 3 < 32) {
                    const uint32_t so = (uint32_t)((c + 3) & 3) * RST;
                    CP_ASYNC16(dstAh + so, ahg + (c + 3) * 64);
                    CP_ASYNC16(dstAl + so, alg + (c + 3) * 64);
                    CP_ASYNC16(dstWl + so, wlg + (c + 3) * 64);
                    CP_COMMIT();
                }

                const uint32_t soff = (uint32_t)(c & 3) * RST;
                const uint32_t c4 = (uint32_t)(c << 2);
#pragma unroll
                for (int kk = 0; kk < 2; ++kk) {
                    uint32_t ah[2][4], al[2][4], bh[4], bl[4];
                    LDMX4(ah[0], a_addr[0][kk] + soff);
                    LDMX4(ah[1], a_addr[1][kk] + soff);
                    LDMX4(al[0], a_addr[0][kk] + soff + 4096u);
                    LDMX4(al[1], a_addr[1][kk] + soff + 4096u);
                    LDMX4(bl, bl_addr[kk] + soff);
                    {
                        uint32_t bhaddr = bh_rowbase + (((c4 + bh_k[kk]) ^ bh_rowx) << 4);
                        LDMX4(bh, bhaddr);
                    }
#pragma unroll
                    for (int mi = 0; mi < 2; ++mi) {
#pragma unroll
                        for (int nf = 0; nf < 2; ++nf) {
                            const int p = nf << 1;
                            MMA_BF16(acc[mi][nf], ah[mi], bh[p], bh[p + 1]);
                            MMA_BF16(acc[mi][nf], ah[mi], bl[p], bl[p + 1]);
                            MMA_BF16(acc[mi][nf], al[mi], bh[p], bh[p + 1]);
                        }
                    }
                }
            }
            __syncthreads();
        }

        // gate fragments -> smem (64 x 72 fp32)
#pragma unroll
        for (int mi = 0; mi < 2; ++mi)
#pragma unroll
            for (int h2 = 0; h2 < 2; ++h2) {
                const int row = warp_m * 32 + mi * 16 + grp + h2 * 8;
#pragma unroll
                for (int nf = 0; nf < 2; ++nf) {
                    const int col = warp_n * 16 + nf * 8 + cl;
                    gsm[row * 72 + col]     = acc[mi][nf][h2 * 2];
                    gsm[row * 72 + col + 1] = acc[mi][nf][h2 * 2 + 1];
                }
            }
        __syncthreads();

        // fused cell: gates = gsm + gx[t] (prefetched); c in regs; write h {fp32, hi, lo}
#pragma unroll
        for (int it = 0; it < 4; ++it) {
            const int idx = it * 256 + tid;
            const int crow = idx >> 4;
            const int cj = idx & 15;
            const int rg = m0 + crow;
            const int jg = (n0 >> 2) + cj;
            float4 ga = *(const float4*)(gsm + crow * 72 + cj * 4);
            float4 gv = gvr[it];
            float gi = sigm(ga.x + gv.x);
            float gf = sigm(ga.y + gv.y);
            float gg = tanhf(ga.z + gv.z);
            float go = sigm(ga.w + gv.w);
            float cc = gf * cstate[it] + gi * gg;
            cstate[it] = cc;
            float hv = go * tanhf(cc);
            const size_t off = (size_t)t * BB * 1024 + (size_t)rg * 1024 + jg;
            hf[off] = hv;
            __nv_bfloat16 hh = __float2bfloat16(hv);
            hhi[off] = hh;
            hlo[off] = __float2bfloat16(hv - __bfloat162float(hh));
        }

        grid_barrier();
    }
}

// ---------------- FFMA2 tile macros (remaining small GEMMs) ----------------
#define PA 66
#define PW 68
#define STORE_TILE(buf)                                            \
    do {                                                           \
        Ad[buf][lk + 0][li] = pk2(a_reg.x, a_reg.x);               \
        Ad[buf][lk + 1][li] = pk2(a_reg.y, a_reg.y);               \
        Ad[buf][lk + 2][li] = pk2(a_reg.z, a_reg.z);               \
        Ad[buf][lk + 3][li] = pk2(a_reg.w, a_reg.w);               \
        Ws[buf][lk + 0][li] = w_reg.x;                             \
        Ws[buf][lk + 1][li] = w_reg.y;                             \
        Ws[buf][lk + 2][li] = w_reg.z;                             \
        Ws[buf][lk + 3][li] = w_reg.w;                             \
    } while (0)

#define COMPUTE_TILE(buf)                                                     \
    do {                                                                      \
        _Pragma("unroll")                                                     \
        for (int k = 0; k < 16; ++k) {                                        \
            ulonglong2 a01 = *(const ulonglong2*)&Ad[buf][k][(ty << 2)];      \
            ulonglong2 a23 = *(const ulonglong2*)&Ad[buf][k][(ty << 2) + 2];  \
            ulonglong2 w01 = *(const ulonglong2*)&Ws[buf][k][(tx << 2)];      \
            acc[0][0] = ffma2(a01.x, w01.x, acc[0][0]);                       \
            acc[0][1] = ffma2(a01.x, w01.y, acc[0][1]);                       \
            acc[1][0] = ffma2(a01.y, w01.x, acc[1][0]);                       \
            acc[1][1] = ffma2(a01.y, w01.y, acc[1][1]);                       \
            acc[2][0] = ffma2(a23.x, w01.x, acc[2][0]);                       \
            acc[2][1] = ffma2(a23.x, w01.y, acc[2][1]);                       \
            acc[3][0] = ffma2(a23.y, w01.x, acc[3][0]);                       \
            acc[3][1] = ffma2(a23.y, w01.y, acc[3][1]);                       \
        }                                                                     \
    } while (0)

// amode: 0 = A row m; 1 = z-gather (m=s*BB+b reads z row b*SSEQ+s)
// act: 0 = none; 1 = tanh
__global__ __launch_bounds__(256, 2)
void gemm_nt(const float* __restrict__ A, const float* __restrict__ W,
             const float* __restrict__ bias, float* __restrict__ C,
             int M, int N, int K, int ldw, int amode, int act)
{
    __shared__ unsigned long long Ad[2][16][PA];
    __shared__ float Ws[2][16][PW];

    const int tid = threadIdx.x;
    const int m0 = blockIdx.y << 6;
    const int n0 = blockIdx.x << 6;

    const int li = tid >> 2;
    const int lk = (tid & 3) << 2;
    const int ty = tid >> 4;
    const int tx = tid & 15;

    const int m = m0 + li;
    const float* arow;
    if (amode == 0) {
        arow = A + (size_t)m * K;
    } else {
        int b = m & (BB - 1), s = m >> 7;
        arow = A + ((size_t)b * SSEQ + s) * K;
    }
    arow += lk;
    const float* wrow = W + (size_t)(n0 + li) * ldw + lk;

    const int nkt = K >> 4;
    float4 a_reg = ldcg4(arow);
    float4 w_reg = ldcg4(wrow);
    STORE_TILE(0);
    __syncthreads();

    unsigned long long acc[4][2];
#pragma unroll
    for (int r = 0; r < 4; ++r) { acc[r][0] = 0ull; acc[r][1] = 0ull; }

    for (int kt = 0; kt < nkt; ++kt) {
        const int cur = kt & 1;
        if (kt + 1 < nkt) {
            a_reg = ldcg4(arow + (size_t)(kt + 1) * 16);
            w_reg = ldcg4(wrow + (size_t)(kt + 1) * 16);
        }
        COMPUTE_TILE(cur);
        if (kt + 1 < nkt) STORE_TILE(cur ^ 1);
        __syncthreads();
    }

#pragma unroll
    for (int r = 0; r < 4; ++r) {
        const int row = m0 + (ty << 2) + r;
#pragma unroll
        for (int p = 0; p < 2; ++p) {
            const int col = n0 + (tx << 2) + (p << 1);
            float2 v = upk2(acc[r][p]);
            if (bias) { v.x += bias[col]; v.y += bias[col + 1]; }
            if (act)  { v.x = tanhf(v.x); v.y = tanhf(v.y); }
            *(float2*)(C + (size_t)row * N + col) = v;
        }
    }
}

// ---------------- one-time weight convert: fp32 -> bf16 hi/lo ----------------
__global__ void convert_w(const float* __restrict__ in,
                          __nv_bfloat16* __restrict__ hi, __nv_bfloat16* __restrict__ lo,
                          int ldk, int K, int doperm, int k0)
{
    int ro = blockIdx.x;
    int sr = doperm ? ((ro & 3) * 1024 + (ro >> 2)) : ro;
    const float* s = in + (size_t)sr * ldk + k0;
    for (int k = threadIdx.x * 4; k < K; k += blockDim.x * 4) {
        float4 v = __ldcg((const float4*)(s + k));
        uint32_t hp0, lp0, hp1, lp1;
        split2(v.x, v.y, hp0, lp0);
        split2(v.z, v.w, hp1, lp1);
        *(uint2*)(hi + (size_t)ro * K + k) = make_uint2(hp0, hp1);
        *(uint2*)(lo + (size_t)ro * K + k) = make_uint2(lp0, lp1);
    }
}

// all three gate-permuted bias sums in one launch (i in [0, 12288))
__global__ void addperm3(const float* a0, const float* b0,
                         const float* a1, const float* b1,
                         const float* a2, const float* b2,
                         float* __restrict__ o)
{
    int i = blockIdx.x * blockDim.x + threadIdx.x;
    int sec = i >> 12;
    int li = i & 4095;
    int j = li >> 2, g = li & 3;
    int s = g * 1024 + j;
    const float* a = sec == 0 ? a0 : (sec == 1 ? a1 : a2);
    const float* b = sec == 0 ? b0 : (sec == 1 ? b1 : b2);
    o[i] = a[s] + b[s];
}

// ---------------- host ----------------
extern "C" void kernel_launch(void* const* d_in, const int* in_sizes, int n_in,
                              void* d_out, int out_size)
{
    const float* z      = (const float*)d_in[0];
    const float* x      = (const float*)d_in[1];
    const float* fcz_w  = (const float*)d_in[2];
    const float* fcz_b  = (const float*)d_in[3];
    const float* c_wih  = (const float*)d_in[4];
    const float* c_whh  = (const float*)d_in[5];
    const float* c_bih  = (const float*)d_in[6];
    const float* c_bhh  = (const float*)d_in[7];
    const float* fcc_w  = (const float*)d_in[8];
    const float* fcc_b  = (const float*)d_in[9];
    const float* d0_wih = (const float*)d_in[10];
    const float* d0_whh = (const float*)d_in[11];
    const float* d0_bih = (const float*)d_in[12];
    const float* d0_bhh = (const float*)d_in[13];
    const float* d1_wih = (const float*)d_in[14];
    const float* d1_whh = (const float*)d_in[15];
    const float* d1_bih = (const float*)d_in[16];
    const float* d1_bhh = (const float*)d_in[17];
    const float* out_w  = (const float*)d_in[18];
    const float* out_b  = (const float*)d_in[19];
    float* out = (float*)d_out;

    float *cin, *gxc, *condh, *emb, *gxe, *gx, *h0, *h1, *bsum_p;
    __nv_bfloat16 *hhi, *hlo;
    __nv_bfloat16 *cwih_hi, *cwih_lo, *cwhh_hi, *cwhh_lo;
    __nv_bfloat16 *d0wih_hi, *d0wih_lo, *d0wihE_hi, *d0wihE_lo, *d0whh_hi, *d0whh_lo;
    __nv_bfloat16 *d1wih_hi, *d1wih_lo, *d1whh_hi, *d1whh_lo, *outw_hi, *outw_lo;
    cudaGetSymbolAddress((void**)&cin,       g_cin);
    cudaGetSymbolAddress((void**)&gxc,       g_gxc);
    cudaGetSymbolAddress((void**)&condh,     g_condh);
    cudaGetSymbolAddress((void**)&emb,       g_emb);
    cudaGetSymbolAddress((void**)&gxe,       g_gxe);
    cudaGetSymbolAddress((void**)&gx,        g_gx);
    cudaGetSymbolAddress((void**)&h0,        g_h0);
    cudaGetSymbolAddress((void**)&h1,        g_h1);
    cudaGetSymbolAddress((void**)&bsum_p,    g_bsum_p);
    cudaGetSymbolAddress((void**)&hhi,       g_hhi);
    cudaGetSymbolAddress((void**)&hlo,       g_hlo);
    cudaGetSymbolAddress((void**)&cwih_hi,   g_cwih_hi);
    cudaGetSymbolAddress((void**)&cwih_lo,   g_cwih_lo);
    cudaGetSymbolAddress((void**)&cwhh_hi,   g_cwhh_hi);
    cudaGetSymbolAddress((void**)&cwhh_lo,   g_cwhh_lo);
    cudaGetSymbolAddress((void**)&d0wih_hi,  g_d0wih_hi);
    cudaGetSymbolAddress((void**)&d0wih_lo,  g_d0wih_lo);
    cudaGetSymbolAddress((void**)&d0wihE_hi, g_d0wihE_hi);
    cudaGetSymbolAddress((void**)&d0wihE_lo, g_d0wihE_lo);
    cudaGetSymbolAddress((void**)&d0whh_hi,  g_d0whh_hi);
    cudaGetSymbolAddress((void**)&d0whh_lo,  g_d0whh_lo);
    cudaGetSymbolAddress((void**)&d1wih_hi,  g_d1wih_hi);
    cudaGetSymbolAddress((void**)&d1wih_lo,  g_d1wih_lo);
    cudaGetSymbolAddress((void**)&d1whh_hi,  g_d1whh_hi);
    cudaGetSymbolAddress((void**)&d1whh_lo,  g_d1whh_lo);
    cudaGetSymbolAddress((void**)&outw_hi,   g_outw_hi);
    cudaGetSymbolAddress((void**)&outw_lo,   g_outw_lo);

    cudaFuncSetAttribute(gemm_mma, cudaFuncAttributeMaxDynamicSharedMemorySize, 2 * MST);
    cudaFuncSetAttribute(lstm_rec_mma, cudaFuncAttributeMaxDynamicSharedMemorySize, RSMEM);

    dim3 blk(256);

    // one-time converts (gate-permuted where consumed in perm order)
    convert_w<<<4096, 256>>>(c_wih,  cwih_hi,  cwih_lo,  HC, HC, 1, 0);
    convert_w<<<4096, 256>>>(c_whh,  cwhh_hi,  cwhh_lo,  HC, HC, 1, 0);
    convert_w<<<4096, 256>>>(d0_wih, d0wih_hi, d0wih_lo, VV + EE, VV, 1, 0);
    convert_w<<<4096, 256>>>(d0_wih, d0wihE_hi, d0wihE_lo, VV + EE, EE, 1, VV);
    convert_w<<<4096, 256>>>(d0_whh, d0whh_hi, d0whh_lo, HD, HD, 1, 0);
    convert_w<<<4096, 256>>>(d1_wih, d1wih_hi, d1wih_lo, HD, HD, 1, 0);
    convert_w<<<4096, 256>>>(d1_whh, d1whh_hi, d1whh_lo, HD, HD, 1, 0);
    convert_w<<<1024, 256>>>(out_w,  outw_hi,  outw_lo,  HD, HD, 0, 0);
    addperm3<<<48, 256>>>(c_bih, c_bhh, d0_bih, d0_bhh, d1_bih, d1_bhh, bsum_p);

    // ---- conductor ----
    gemm_nt<<<dim3(HC / 64, (SSEQ * BB) / 64), blk>>>(
        z, fcz_w, fcz_b, cin, SSEQ * BB, HC, ZZ, ZZ, 1, 0);
    gemm_mma<<<dim3(4 * HC / 128, (SSEQ * BB) / 128), blk, 2 * MST>>>(
        cin, cwih_hi, cwih_lo, bsum_p, nullptr, gxc, HC, 4 * HC, 0, 0);
    lstm_rec_mma<<<NBLK, blk, RSMEM>>>(cwhh_hi, cwhh_lo, gxc, condh, hhi, hlo, SSEQ);
    gemm_nt<<<dim3(EE / 64, (SSEQ * BB) / 64), blk>>>(
        condh, fcc_w, fcc_b, emb, SSEQ * BB, EE, HC, HC, 0, 1);
    gemm_mma<<<dim3(4 * HD / 128, (SSEQ * BB) / 128), blk, 2 * MST>>>(
        emb, d0wihE_hi, d0wihE_lo, bsum_p + 4096, nullptr, gxe, EE, 4 * HD, 0, 0);

    // ---- decoder layer 0 ----
    gemm_mma<<<dim3(4 * HD / 128, (TT * BB) / 128), blk, 2 * MST>>>(
        x, d0wih_hi, d0wih_lo, nullptr, gxe, gx, VV, 4 * HD, 2, 0);
    lstm_rec_mma<<<NBLK, blk, RSMEM>>>(d0whh_hi, d0whh_lo, gx, h0, hhi, hlo, TT);

    // ---- decoder layer 1 ----
    gemm_mma<<<dim3(4 * HD / 128, (TT * BB) / 128), blk, 2 * MST>>>(
        h0, d1wih_hi, d1wih_lo, bsum_p + 8192, nullptr, gx, HD, 4 * HD, 0, 0);
    lstm_rec_mma<<<NBLK, blk, RSMEM>>>(d1whh_hi, d1whh_lo, gx, h1, hhi, hlo, TT);

    // ---- output projection (time-major -> [B,T,V]) ----
    gemm_mma<<<dim3(VV / 128, (TT * BB) / 128), blk, 2 * MST>>>(
        h1, outw_hi, outw_lo, out_b, nullptr, out, HD, VV, 0, 1);
}

// round 15
// speedup vs baseline: 1.1249x; 1.0023x over previous
#include <cuda_runtime.h>
#include <cuda_bf16.h>
#include <cstdint>

#define BB 128
#define SSEQ 16
#define TT 256
#define ZZ 512
#define HC 1024
#define EE 512
#define HD 1024
#define VV 1024
#define NBLK 128

// ---------------- scratch (device globals; zero-init at module load) ----------------
__device__ float g_zero[BB * HD];                       // never written: stays zero
__device__ float g_cin[SSEQ * BB * HC];
__device__ float g_gxc[SSEQ * BB * 4 * HC];             // perm gate order
__device__ float g_condh[SSEQ * BB * HC];
__device__ float g_emb[SSEQ * BB * EE];
__device__ float g_gxe[SSEQ * BB * 4 * HD];             // perm
__device__ float g_gx[TT * BB * 4 * HD];                // perm
__device__ float g_h0[TT * BB * HD];
__device__ float g_h1[TT * BB * HD];
__device__ float g_bsum_p[3 * 4 * HD];
// bf16 h history (hi/lo split), shared across the three recurrences (serial launches)
__device__ __align__(16) __nv_bfloat16 g_hhi[TT * BB * HD];
__device__ __align__(16) __nv_bfloat16 g_hlo[TT * BB * HD];
// bf16 hi/lo split weights (mma consumers)
__device__ __align__(16) __nv_bfloat16 g_fczw_hi[HC * ZZ];
__device__ __align__(16) __nv_bfloat16 g_fczw_lo[HC * ZZ];
__device__ __align__(16) __nv_bfloat16 g_fccw_hi[EE * HC];
__device__ __align__(16) __nv_bfloat16 g_fccw_lo[EE * HC];
__device__ __align__(16) __nv_bfloat16 g_cwih_hi[4 * HC * HC];
__device__ __align__(16) __nv_bfloat16 g_cwih_lo[4 * HC * HC];
__device__ __align__(16) __nv_bfloat16 g_cwhh_hi[4 * HC * HC];
__device__ __align__(16) __nv_bfloat16 g_cwhh_lo[4 * HC * HC];
__device__ __align__(16) __nv_bfloat16 g_d0wih_hi[4 * HD * VV];
__device__ __align__(16) __nv_bfloat16 g_d0wih_lo[4 * HD * VV];
__device__ __align__(16) __nv_bfloat16 g_d0wihE_hi[4 * HD * EE];
__device__ __align__(16) __nv_bfloat16 g_d0wihE_lo[4 * HD * EE];
__device__ __align__(16) __nv_bfloat16 g_d0whh_hi[4 * HD * HD];
__device__ __align__(16) __nv_bfloat16 g_d0whh_lo[4 * HD * HD];
__device__ __align__(16) __nv_bfloat16 g_d1wih_hi[4 * HD * HD];
__device__ __align__(16) __nv_bfloat16 g_d1wih_lo[4 * HD * HD];
__device__ __align__(16) __nv_bfloat16 g_d1whh_hi[4 * HD * HD];
__device__ __align__(16) __nv_bfloat16 g_d1whh_lo[4 * HD * HD];
__device__ __align__(16) __nv_bfloat16 g_outw_hi[VV * HD];
__device__ __align__(16) __nv_bfloat16 g_outw_lo[VV * HD];

// split grid-barrier state: one independent barrier per m-half (64 CTAs each)
__device__ volatile unsigned int g_bar_gen2[2];
__device__ unsigned int g_bar_cnt2[2];

// ---------------- helpers ----------------
__device__ __forceinline__ float4 ldcg4(const float* p) {
    return __ldcg((const float4*)(p));
}
__device__ __forceinline__ float sigm(float x) { return 1.f / (1.f + expf(-x)); }

__device__ __forceinline__ uint32_t smem_u32(const void* p) {
    uint32_t a;
    asm("{ .reg .u64 t; cvta.to.shared.u64 t, %1; cvt.u32.u64 %0, t; }" : "=r"(a) : "l"(p));
    return a;
}
__device__ __forceinline__ uint32_t pack_bf16(__nv_bfloat16 a, __nv_bfloat16 b) {
    return (uint32_t)__bfloat16_as_ushort(a) | ((uint32_t)__bfloat16_as_ushort(b) << 16);
}
__device__ __forceinline__ void split2(float x, float y, uint32_t& hp, uint32_t& lp) {
    __nv_bfloat16 hx = __float2bfloat16(x), hy = __float2bfloat16(y);
    __nv_bfloat16 lx = __float2bfloat16(x - __bfloat162float(hx));
    __nv_bfloat16 ly = __float2bfloat16(y - __bfloat162float(hy));
    hp = pack_bf16(hx, hy);
    lp = pack_bf16(lx, ly);
}

// ---------------- mma.sync (HMMA) + cp.async primitives — baseline PTX ----------------
#define MMA_BF16(d, a, b0, b1)                                                  \
    asm volatile("mma.sync.aligned.m16n8k16.row.col.f32.bf16.bf16.f32 "         \
        "{%0,%1,%2,%3}, {%4,%5,%6,%7}, {%8,%9}, {%0,%1,%2,%3};"                 \
        : "+f"((d)[0]), "+f"((d)[1]), "+f"((d)[2]), "+f"((d)[3])                \
        : "r"((a)[0]), "r"((a)[1]), "r"((a)[2]), "r"((a)[3]), "r"(b0), "r"(b1))

#define LDMX4(r, addr)                                                          \
    asm volatile("ldmatrix.sync.aligned.m8n8.x4.shared.b16 {%0,%1,%2,%3}, [%4];" \
        : "=r"((r)[0]), "=r"((r)[1]), "=r"((r)[2]), "=r"((r)[3]) : "r"(addr))

#define CP_ASYNC16(dst, src) \
    asm volatile("cp.async.cg.shared.global [%0], [%1], 16;" :: "r"(dst), "l"(src))
#define CP_COMMIT() asm volatile("cp.async.commit_group;" ::: "memory")
#define CP_WAIT(n)  asm volatile("cp.async.wait_group %0;" :: "n"(n) : "memory")

// ---------------- HMMA GEMM: C = gather(A)[M,K] * W[N,K]^T (+bias)(+Cin)(tanh) ------
// A fp32 split to bf16 hi/lo in transit; W pre-split. 128x128 tile, 8 warps, K-chunk 32.
// amode: 0 = A row m; 1 = z-gather (row b*SSEQ+s, K=512); 2 = prev-x gather.
// Cin: row (t>>4)*BB+b. cmode: 0 = row m; 1 = row (b*TT+t). act: 1 = tanh.
#define MST 32768
__global__ __launch_bounds__(256, 1)
void gemm_mma(const float* __restrict__ A,
              const __nv_bfloat16* __restrict__ Whi,
              const __nv_bfloat16* __restrict__ Wlo,
              const float* __restrict__ bias, const float* __restrict__ Cin,
              float* __restrict__ C,
              int K, int N, int amode, int cmode, int act)
{
    extern __shared__ char sm[];
    const uint32_t sb = smem_u32(sm);
    const int tid = threadIdx.x;
    const int lane = tid & 31;
    const int wid = tid >> 5;
    const int warp_m = wid & 1;
    const int warp_n = wid >> 1;
    const int m0 = blockIdx.y << 7;
    const int n0 = blockIdx.x << 7;

    const int lrow = tid >> 1;
    const int half = tid & 1;

    const float* arow;
    {
        int m = m0 + lrow;
        if (amode == 0) {
            arow = A + (size_t)m * K;
        } else if (amode == 1) {
            int b = m & 127, s = m >> 7;
            arow = A + ((size_t)b * SSEQ + s) * K;
        } else {
            int t = m >> 7, b = m & 127;
            arow = (t == 0) ? g_zero : A + ((size_t)b * TT + (t - 1)) * 1024;
        }
    }
    const uint4* whrow = (const uint4*)(Whi + (size_t)(n0 + lrow) * K);
    const uint4* wlrow = (const uint4*)(Wlo + (size_t)(n0 + lrow) * K);

    const uint32_t sst0 = (uint32_t)lrow * 64u + (uint32_t)(((half * 2)     ^ (lrow & 3)) << 4);
    const uint32_t sst1 = (uint32_t)lrow * 64u + (uint32_t)(((half * 2 + 1) ^ (lrow & 3)) << 4);

    uint32_t a_addr[4][2], b_addr[2][2];
    {
        int ar = warp_m * 64 + (lane & 7) + (((lane >> 3) & 1) << 3);
        int akh = lane >> 4;
        int br = warp_n * 32 + (lane & 7) + ((lane >> 4) << 3);
        int bkh = (lane >> 3) & 1;
#pragma unroll
        for (int mi = 0; mi < 4; ++mi)
#pragma unroll
            for (int kk = 0; kk < 2; ++kk) {
                int row = ar + mi * 16;
                a_addr[mi][kk] = sb + (uint32_t)row * 64u
                               + (uint32_t)((((kk << 1) | akh) ^ (row & 3)) << 4);
            }
#pragma unroll
        for (int ng = 0; ng < 2; ++ng)
#pragma unroll
            for (int kk = 0; kk < 2; ++kk) {
                int row = br + ng * 16;
                b_addr[ng][kk] = sb + 16384u + (uint32_t)row * 64u
                               + (uint32_t)((((kk << 1) | bkh) ^ (row & 3)) << 4);
            }
    }

    float acc[4][4][4];
#pragma unroll
    for (int mi = 0; mi < 4; ++mi)
#pragma unroll
        for (int nf = 0; nf < 4; ++nf)
#pragma unroll
            for (int q = 0; q < 4; ++q) acc[mi][nf][q] = 0.f;

    const int NC = K >> 5;
    float4 pa[4];
    uint4 pwh[2], pwl[2];

#pragma unroll
    for (int i = 0; i < 4; ++i) pa[i] = ldcg4(arow + half * 16 + i * 4);
#pragma unroll
    for (int j = 0; j < 2; ++j) {
        pwh[j] = __ldcg(whrow + half * 2 + j);
        pwl[j] = __ldcg(wlrow + half * 2 + j);
    }
    {
        uint32_t h0a, l0a, h0b, l0b, h1a, l1a, h1b, l1b;
        split2(pa[0].x, pa[0].y, h0a, l0a); split2(pa[0].z, pa[0].w, h0b, l0b);
        split2(pa[1].x, pa[1].y, h1a, l1a); split2(pa[1].z, pa[1].w, h1b, l1b);
        *(uint4*)(sm + sst0)         = make_uint4(h0a, h0b, h1a, h1b);
        *(uint4*)(sm + 8192 + sst0)  = make_uint4(l0a, l0b, l1a, l1b);
        split2(pa[2].x, pa[2].y, h0a, l0a); split2(pa[2].z, pa[2].w, h0b, l0b);
        split2(pa[3].x, pa[3].y, h1a, l1a); split2(pa[3].z, pa[3].w, h1b, l1b);
        *(uint4*)(sm + sst1)         = make_uint4(h0a, h0b, h1a, h1b);
        *(uint4*)(sm + 8192 + sst1)  = make_uint4(l0a, l0b, l1a, l1b);
        *(uint4*)(sm + 16384 + sst0) = pwh[0];
        *(uint4*)(sm + 16384 + sst1) = pwh[1];
        *(uint4*)(sm + 24576 + sst0) = pwl[0];
        *(uint4*)(sm + 24576 + sst1) = pwl[1];
    }
    __syncthreads();

    for (int c = 0; c < NC; ++c) {
        const int cur = c & 1;
        const uint32_t soff = (uint32_t)cur * MST;
        if (c + 1 < NC) {
#pragma unroll
            for (int i = 0; i < 4; ++i)
                pa[i] = ldcg4(arow + (c + 1) * 32 + half * 16 + i * 4);
#pragma unroll
            for (int j = 0; j < 2; ++j) {
                pwh[j] = __ldcg(whrow + (c + 1) * 4 + half * 2 + j);
                pwl[j] = __ldcg(wlrow + (c + 1) * 4 + half * 2 + j);
            }
        }

#pragma unroll
        for (int kk = 0; kk < 2; ++kk) {
            uint32_t ah[4][4], al[4][4], bh[2][4], bl[2][4];
#pragma unroll
            for (int mi = 0; mi < 4; ++mi) {
                LDMX4(ah[mi], a_addr[mi][kk] + soff);
                LDMX4(al[mi], a_addr[mi][kk] + soff + 8192u);
            }
#pragma unroll
            for (int ng = 0; ng < 2; ++ng) {
                LDMX4(bh[ng], b_addr[ng][kk] + soff);
                LDMX4(bl[ng], b_addr[ng][kk] + soff + 8192u);
            }
#pragma unroll
            for (int mi = 0; mi < 4; ++mi) {
#pragma unroll
                for (int nf = 0; nf < 4; ++nf) {
                    const int ng = nf >> 1;
                    const int p = (nf & 1) << 1;
                    MMA_BF16(acc[mi][nf], ah[mi], bh[ng][p], bh[ng][p + 1]);
                    MMA_BF16(acc[mi][nf], ah[mi], bl[ng][p], bl[ng][p + 1]);
                    MMA_BF16(acc[mi][nf], al[mi], bh[ng][p], bh[ng][p + 1]);
                }
            }
        }

        if (c + 1 < NC) {
            char* d = sm + (cur ^ 1) * MST;
            uint32_t h0a, l0a, h0b, l0b, h1a, l1a, h1b, l1b;
            split2(pa[0].x, pa[0].y, h0a, l0a); split2(pa[0].z, pa[0].w, h0b, l0b);
            split2(pa[1].x, pa[1].y, h1a, l1a); split2(pa[1].z, pa[1].w, h1b, l1b);
            *(uint4*)(d + sst0)         = make_uint4(h0a, h0b, h1a, h1b);
            *(uint4*)(d + 8192 + sst0)  = make_uint4(l0a, l0b, l1a, l1b);
            split2(pa[2].x, pa[2].y, h0a, l0a); split2(pa[2].z, pa[2].w, h0b, l0b);
            split2(pa[3].x, pa[3].y, h1a, l1a); split2(pa[3].z, pa[3].w, h1b, l1b);
            *(uint4*)(d + sst1)         = make_uint4(h0a, h0b, h1a, h1b);
            *(uint4*)(d + 8192 + sst1)  = make_uint4(l0a, l0b, l1a, l1b);
            *(uint4*)(d + 16384 + sst0) = pwh[0];
            *(uint4*)(d + 16384 + sst1) = pwh[1];
            *(uint4*)(d + 24576 + sst0) = pwl[0];
            *(uint4*)(d + 24576 + sst1) = pwl[1];
        }
        __syncthreads();
    }

    const int grp = lane >> 2;
    const int cl  = (lane & 3) << 1;
#pragma unroll
    for (int mi = 0; mi < 4; ++mi) {
#pragma unroll
        for (int h = 0; h < 2; ++h) {
            const int row = m0 + warp_m * 64 + mi * 16 + grp + h * 8;
            size_t coff;
            if (cmode == 0) {
                coff = (size_t)row * N;
            } else {
                int t = row >> 7, b = row & 127;
                coff = ((size_t)b * TT + t) * N;
            }
            size_t cinoff = 0;
            if (Cin) {
                int cr = ((row >> 11) << 7) + (row & 127);
                cinoff = (size_t)cr * N;
            }
#pragma unroll
            for (int nf = 0; nf < 4; ++nf) {
                const int col = n0 + warp_n * 32 + nf * 8 + cl;
                float2 v = make_float2(acc[mi][nf][h * 2], acc[mi][nf][h * 2 + 1]);
                if (bias) { v.x += bias[col]; v.y += bias[col + 1]; }
                if (Cin)  {
                    float2 ci = *(const float2*)(Cin + cinoff + col);
                    v.x += ci.x; v.y += ci.y;
                }
                if (act) { v.x = tanhf(v.x); v.y = tanhf(v.y); }
                *(float2*)(C + coff + col) = v;
            }
        }
    }
}

// ---------------- split grid barrier: independent per m-half (64 CTAs each) ----------------
__device__ __forceinline__ void grid_barrier_half(int hf)
{
    __syncthreads();
    __threadfence();
    if (threadIdx.x == 0) {
        unsigned int gen = g_bar_gen2[hf];
        if (atomicAdd(&g_bar_cnt2[hf], 1u) == 63u) {
            g_bar_cnt2[hf] = 0u;
            __threadfence();
            g_bar_gen2[hf] = gen + 1u;
        } else {
            while (g_bar_gen2[hf] == gen) { __nanosleep(64); }
        }
    }
    __syncthreads();
}

// ---------------- persistent HMMA LSTM recurrence (persistent Whi; split barrier) ----------
// 128 CTAs: tile 64 rows (m0 = (bx>>6)*64) x 64 perm-cols (n0 = (bx&63)*64), K=1024.
// Whi slice (64 rows x 2048B) persisted in smem (^(row&7) swizzle); Wlo/Ahi/Alo streamed
// via 4-stage cp.async (12KB stages). The two m-halves synchronize independently.
#define RST 12288
#define RGOFF (4 * RST)                      // gates: 64 x 72 fp32
#define RWHI (RGOFF + 64 * 72 * 4)           // persistent Whi: 64 x 2048B
#define RSMEM (RWHI + 64 * 2048)             // 198656 B
__global__ __launch_bounds__(256, 1)
void lstm_rec_mma(const __nv_bfloat16* __restrict__ Whi,
                  const __nv_bfloat16* __restrict__ Wlo,
                  const float* __restrict__ gx,
                  float* __restrict__ hf,
                  __nv_bfloat16* __restrict__ hhi,
                  __nv_bfloat16* __restrict__ hlo,
                  int T)
{
    extern __shared__ char sm[];
    const uint32_t sb = smem_u32(sm);
    float* gsm = (float*)(sm + RGOFF);
    const int tid = threadIdx.x;
    const int lane = tid & 31;
    const int wid = tid >> 5;
    const int warp_m = wid & 1;
    const int warp_n = wid >> 1;
    const int bx = blockIdx.x;
    const int mhalf = bx >> 6;              // 0 or 1
    const int m0 = mhalf << 6;
    const int n0 = (bx & 63) << 6;          // 0..4032 (perm cols)

    // loader: thread -> (row 0..63, 16B quad 0..3); stage swizzle chunk ^= row&3
    const int lrow = tid >> 2;
    const int quad = tid & 3;
    const uint32_t sst = (uint32_t)lrow * 64u + (uint32_t)((quad ^ (lrow & 3)) << 4);
    const uint32_t dstAh = sb + sst;
    const uint32_t dstAl = sb + 4096u + sst;
    const uint32_t dstWl = sb + 8192u + sst;

    const char* wlg = (const char*)(Wlo + (size_t)(n0 + lrow) * 1024) + quad * 16;

    // one-time: persist Whi slice into smem (64 rows x 128 16B-units, ^(r&7) swizzle)
    for (int i = tid; i < 64 * 128; i += 256) {
        int r = i >> 7, c16 = i & 127;
        uint4 v = __ldcg((const uint4*)(Whi + (size_t)(n0 + r) * 1024) + c16);
        *(uint4*)(sm + RWHI + r * 2048 + ((c16 ^ (r & 7)) << 4)) = v;
    }

    uint32_t a_addr[2][2], bl_addr[2];
    uint32_t bh_rowbase, bh_rowx, bh_k[2];
    {
        int ar = warp_m * 32 + (lane & 7) + (((lane >> 3) & 1) << 3);
        int akh = lane >> 4;
#pragma unroll
        for (int mi = 0; mi < 2; ++mi)
#pragma unroll
            for (int kk = 0; kk < 2; ++kk) {
                int row = ar + mi * 16;
                a_addr[mi][kk] = sb + (uint32_t)row * 64u
                               + (uint32_t)((((kk << 1) | akh) ^ (row & 3)) << 4);
            }
        int br = warp_n * 16 + (lane & 7) + ((lane >> 4) << 3);
        int bkh = (lane >> 3) & 1;
#pragma unroll
        for (int kk = 0; kk < 2; ++kk)
            bl_addr[kk] = sb + 8192u + (uint32_t)br * 64u
                        + (uint32_t)((((kk << 1) | bkh) ^ (br & 3)) << 4);
        bh_rowbase = sb + RWHI + (uint32_t)br * 2048u;
        bh_rowx = (uint32_t)(br & 7);
        bh_k[0] = (uint32_t)bkh;             // col16 = c*4 + kk*2 + bkh
        bh_k[1] = (uint32_t)(2 + bkh);
    }
    __syncthreads();   // Whi persisted & visible

    const int grp = lane >> 2;
    const int cl  = (lane & 3) << 1;

    float cstate[4] = {0.f, 0.f, 0.f, 0.f};

    for (int t = 0; t < T; ++t) {
        // prefetch gx[t] for the cell (latency hidden under the GEMM)
        const float* gxt = gx + (size_t)t * BB * 4096;
        float4 gvr[4];
#pragma unroll
        for (int it = 0; it < 4; ++it) {
            const int idx = it * 256 + tid;
            gvr[it] = ldcg4(gxt + (size_t)(m0 + (idx >> 4)) * 4096 + n0 + (idx & 15) * 4);
        }

        float acc[2][2][4];
#pragma unroll
        for (int mi = 0; mi < 2; ++mi)
#pragma unroll
            for (int nf = 0; nf < 2; ++nf)
#pragma unroll
                for (int q = 0; q < 4; ++q) acc[mi][nf][q] = 0.f;

        if (t > 0) {
            const char* ahg = (const char*)(hhi + (size_t)(t - 1) * BB * 1024
                                            + (size_t)(m0 + lrow) * 1024) + quad * 16;
            const char* alg = (const char*)(hlo + (size_t)(t - 1) * BB * 1024
                                            + (size_t)(m0 + lrow) * 1024) + quad * 16;

            // prologue: chunks 0..2 into stages 0..2
#pragma unroll
            for (int s = 0; s < 3; ++s) {
                const uint32_t so = (uint32_t)s * RST;
                CP_ASYNC16(dstAh + so, ahg + s * 64);
                CP_ASYNC16(dstAl + so, alg + s * 64);
                CP_ASYNC16(dstWl + so, wlg + s * 64);
                CP_COMMIT();
            }

            for (int c = 0; c < 32; ++c) {
                if (c <= 29) CP_WAIT(2);
                else if (c == 30) CP_WAIT(1);
                else CP_WAIT(0);
                __syncthreads();

                if (c + 3 < 32) {
                    const uint32_t so = (uint32_t)((c + 3) & 3) * RST;
                    CP_ASYNC16(dstAh + so, ahg + (c + 3) * 64);
                    CP_ASYNC16(dstAl + so, alg + (c + 3) * 64);
                    CP_ASYNC16(dstWl + so, wlg + (c + 3) * 64);
                    CP_COMMIT();
                }

                const uint32_t soff = (uint32_t)(c & 3) * RST;
                const uint32_t c4 = (uint32_t)(c << 2);
#pragma unroll
                for (int kk = 0; kk < 2; ++kk) {
                    uint32_t ah[2][4], al[2][4], bh[4], bl[4];
                    LDMX4(ah[0], a_addr[0][kk] + soff);
                    LDMX4(ah[1], a_addr[1][kk] + soff);
                    LDMX4(al[0], a_addr[0][kk] + soff + 4096u);
                    LDMX4(al[1], a_addr[1][kk] + soff + 4096u);
                    LDMX4(bl, bl_addr[kk] + soff);
                    {
                        uint32_t bhaddr = bh_rowbase + (((c4 + bh_k[kk]) ^ bh_rowx) << 4);
                        LDMX4(bh, bhaddr);
                    }
#pragma unroll
                    for (int mi = 0; mi < 2; ++mi) {
#pragma unroll
                        for (int nf = 0; nf < 2; ++nf) {
                            const int p = nf << 1;
                            MMA_BF16(acc[mi][nf], ah[mi], bh[p], bh[p + 1]);
                            MMA_BF16(acc[mi][nf], ah[mi], bl[p], bl[p + 1]);
                            MMA_BF16(acc[mi][nf], al[mi], bh[p], bh[p + 1]);
                        }
                    }
                }
            }
            __syncthreads();
        }

        // gate fragments -> smem (64 x 72 fp32)
#pragma unroll
        for (int mi = 0; mi < 2; ++mi)
#pragma unroll
            for (int h2 = 0; h2 < 2; ++h2) {
                const int row = warp_m * 32 + mi * 16 + grp + h2 * 8;
#pragma unroll
                for (int nf = 0; nf < 2; ++nf) {
                    const int col = warp_n * 16 + nf * 8 + cl;
                    gsm[row * 72 + col]     = acc[mi][nf][h2 * 2];
                    gsm[row * 72 + col + 1] = acc[mi][nf][h2 * 2 + 1];
                }
            }
        __syncthreads();

        // fused cell: gates = gsm + gx[t] (prefetched); c in regs; write h {fp32, hi, lo}
#pragma unroll
        for (int it = 0; it < 4; ++it) {
            const int idx = it * 256 + tid;
            const int crow = idx >> 4;
            const int cj = idx & 15;
            const int rg = m0 + crow;
            const int jg = (n0 >> 2) + cj;
            float4 ga = *(const float4*)(gsm + crow * 72 + cj * 4);
            float4 gv = gvr[it];
            float gi = sigm(ga.x + gv.x);
            float gf = sigm(ga.y + gv.y);
            float gg = tanhf(ga.z + gv.z);
            float go = sigm(ga.w + gv.w);
            float cc = gf * cstate[it] + gi * gg;
            cstate[it] = cc;
            float hv = go * tanhf(cc);
            const size_t off = (size_t)t * BB * 1024 + (size_t)rg * 1024 + jg;
            hf[off] = hv;
            __nv_bfloat16 hh = __float2bfloat16(hv);
            hhi[off] = hh;
            hlo[off] = __float2bfloat16(hv - __bfloat162float(hh));
        }

        grid_barrier_half(mhalf);
    }
}

// ---------------- one-time weight convert: fp32 -> bf16 hi/lo ----------------
__global__ void convert_w(const float* __restrict__ in,
                          __nv_bfloat16* __restrict__ hi, __nv_bfloat16* __restrict__ lo,
                          int ldk, int K, int doperm, int k0)
{
    int ro = blockIdx.x;
    int sr = doperm ? ((ro & 3) * 1024 + (ro >> 2)) : ro;
    const float* s = in + (size_t)sr * ldk + k0;
    for (int k = threadIdx.x * 4; k < K; k += blockDim.x * 4) {
        float4 v = __ldcg((const float4*)(s + k));
        uint32_t hp0, lp0, hp1, lp1;
        split2(v.x, v.y, hp0, lp0);
        split2(v.z, v.w, hp1, lp1);
        *(uint2*)(hi + (size_t)ro * K + k) = make_uint2(hp0, hp1);
        *(uint2*)(lo + (size_t)ro * K + k) = make_uint2(lp0, lp1);
    }
}

// all three gate-permuted bias sums in one launch (i in [0, 12288))
__global__ void addperm3(const float* a0, const float* b0,
                         const float* a1, const float* b1,
                         const float* a2, const float* b2,
                         float* __restrict__ o)
{
    int i = blockIdx.x * blockDim.x + threadIdx.x;
    int sec = i >> 12;
    int li = i & 4095;
    int j = li >> 2, g = li & 3;
    int s = g * 1024 + j;
    const float* a = sec == 0 ? a0 : (sec == 1 ? a1 : a2);
    const float* b = sec == 0 ? b0 : (sec == 1 ? b1 : b2);
    o[i] = a[s] + b[s];
}

// ---------------- host ----------------
extern "C" void kernel_launch(void* const* d_in, const int* in_sizes, int n_in,
                              void* d_out, int out_size)
{
    const float* z      = (const float*)d_in[0];
    const float* x      = (const float*)d_in[1];
    const float* fcz_w  = (const float*)d_in[2];
    const float* fcz_b  = (const float*)d_in[3];
    const float* c_wih  = (const float*)d_in[4];
    const float* c_whh  = (const float*)d_in[5];
    const float* c_bih  = (const float*)d_in[6];
    const float* c_bhh  = (const float*)d_in[7];
    const float* fcc_w  = (const float*)d_in[8];
    const float* fcc_b  = (const float*)d_in[9];
    const float* d0_wih = (const float*)d_in[10];
    const float* d0_whh = (const float*)d_in[11];
    const float* d0_bih = (const float*)d_in[12];
    const float* d0_bhh = (const float*)d_in[13];
    const float* d1_wih = (const float*)d_in[14];
    const float* d1_whh = (const float*)d_in[15];
    const float* d1_bih = (const float*)d_in[16];
    const float* d1_bhh = (const float*)d_in[17];
    const float* out_w  = (const float*)d_in[18];
    const float* out_b  = (const float*)d_in[19];
    float* out = (float*)d_out;

    float *cin, *gxc, *condh, *emb, *gxe, *gx, *h0, *h1, *bsum_p;
    __nv_bfloat16 *hhi, *hlo;
    __nv_bfloat16 *fczw_hi, *fczw_lo, *fccw_hi, *fccw_lo;
    __nv_bfloat16 *cwih_hi, *cwih_lo, *cwhh_hi, *cwhh_lo;
    __nv_bfloat16 *d0wih_hi, *d0wih_lo, *d0wihE_hi, *d0wihE_lo, *d0whh_hi, *d0whh_lo;
    __nv_bfloat16 *d1wih_hi, *d1wih_lo, *d1whh_hi, *d1whh_lo, *outw_hi, *outw_lo;
    cudaGetSymbolAddress((void**)&cin,       g_cin);
    cudaGetSymbolAddress((void**)&gxc,       g_gxc);
    cudaGetSymbolAddress((void**)&condh,     g_condh);
    cudaGetSymbolAddress((void**)&emb,       g_emb);
    cudaGetSymbolAddress((void**)&gxe,       g_gxe);
    cudaGetSymbolAddress((void**)&gx,        g_gx);
    cudaGetSymbolAddress((void**)&h0,        g_h0);
    cudaGetSymbolAddress((void**)&h1,        g_h1);
    cudaGetSymbolAddress((void**)&bsum_p,    g_bsum_p);
    cudaGetSymbolAddress((void**)&hhi,       g_hhi);
    cudaGetSymbolAddress((void**)&hlo,       g_hlo);
    cudaGetSymbolAddress((void**)&fczw_hi,   g_fczw_hi);
    cudaGetSymbolAddress((void**)&fczw_lo,   g_fczw_lo);
    cudaGetSymbolAddress((void**)&fccw_hi,   g_fccw_hi);
    cudaGetSymbolAddress((void**)&fccw_lo,   g_fccw_lo);
    cudaGetSymbolAddress((void**)&cwih_hi,   g_cwih_hi);
    cudaGetSymbolAddress((void**)&cwih_lo,   g_cwih_lo);
    cudaGetSymbolAddress((void**)&cwhh_hi,   g_cwhh_hi);
    cudaGetSymbolAddress((void**)&cwhh_lo,   g_cwhh_lo);
    cudaGetSymbolAddress((void**)&d0wih_hi,  g_d0wih_hi);
    cudaGetSymbolAddress((void**)&d0wih_lo,  g_d0wih_lo);
    cudaGetSymbolAddress((void**)&d0wihE_hi, g_d0wihE_hi);
    cudaGetSymbolAddress((void**)&d0wihE_lo, g_d0wihE_lo);
    cudaGetSymbolAddress((void**)&d0whh_hi,  g_d0whh_hi);
    cudaGetSymbolAddress((void**)&d0whh_lo,  g_d0whh_lo);
    cudaGetSymbolAddress((void**)&d1wih_hi,  g_d1wih_hi);
    cudaGetSymbolAddress((void**)&d1wih_lo,  g_d1wih_lo);
    cudaGetSymbolAddress((void**)&d1whh_hi,  g_d1whh_hi);
    cudaGetSymbolAddress((void**)&d1whh_lo,  g_d1whh_lo);
    cudaGetSymbolAddress((void**)&outw_hi,   g_outw_hi);
    cudaGetSymbolAddress((void**)&outw_lo,   g_outw_lo);

    cudaFuncSetAttribute(gemm_mma, cudaFuncAttributeMaxDynamicSharedMemorySize, 2 * MST);
    cudaFuncSetAttribute(lstm_rec_mma, cudaFuncAttributeMaxDynamicSharedMemorySize, RSMEM);

    dim3 blk(256);

    // one-time converts (gate-permuted where consumed in perm order)
    convert_w<<<1024, 128>>>(fcz_w, fczw_hi, fczw_lo, ZZ, ZZ, 0, 0);
    convert_w<<<512, 256>>>(fcc_w, fccw_hi, fccw_lo, HC, HC, 0, 0);
    convert_w<<<4096, 256>>>(c_wih,  cwih_hi,  cwih_lo,  HC, HC, 1, 0);
    convert_w<<<4096, 256>>>(c_whh,  cwhh_hi,  cwhh_lo,  HC, HC, 1, 0);
    convert_w<<<4096, 256>>>(d0_wih, d0wih_hi, d0wih_lo, VV + EE, VV, 1, 0);
    convert_w<<<4096, 256>>>(d0_wih, d0wihE_hi, d0wihE_lo, VV + EE, EE, 1, VV);
    convert_w<<<4096, 256>>>(d0_whh, d0whh_hi, d0whh_lo, HD, HD, 1, 0);
    convert_w<<<4096, 256>>>(d1_wih, d1wih_hi, d1wih_lo, HD, HD, 1, 0);
    convert_w<<<4096, 256>>>(d1_whh, d1whh_hi, d1whh_lo, HD, HD, 1, 0);
    convert_w<<<1024, 256>>>(out_w,  outw_hi,  outw_lo,  HD, HD, 0, 0);
    addperm3<<<48, 256>>>(c_bih, c_bhh, d0_bih, d0_bhh, d1_bih, d1_bhh, bsum_p);

    // ---- conductor ----
    gemm_mma<<<dim3(HC / 128, (SSEQ * BB) / 128), blk, 2 * MST>>>(
        z, fczw_hi, fczw_lo, fcz_b, nullptr, cin, ZZ, HC, 1, 0, 0);
    gemm_mma<<<dim3(4 * HC / 128, (SSEQ * BB) / 128), blk, 2 * MST>>>(
        cin, cwih_hi, cwih_lo, bsum_p, nullptr, gxc, HC, 4 * HC, 0, 0, 0);
    lstm_rec_mma<<<NBLK, blk, RSMEM>>>(cwhh_hi, cwhh_lo, gxc, condh, hhi, hlo, SSEQ);
    gemm_mma<<<dim3(EE / 128, (SSEQ * BB) / 128), blk, 2 * MST>>>(
        condh, fccw_hi, fccw_lo, fcc_b, nullptr, emb, HC, EE, 0, 0, 1);
    gemm_mma<<<dim3(4 * HD / 128, (SSEQ * BB) / 128), blk, 2 * MST>>>(
        emb, d0wihE_hi, d0wihE_lo, bsum_p + 4096, nullptr, gxe, EE, 4 * HD, 0, 0, 0);

    // ---- decoder layer 0 ----
    gemm_mma<<<dim3(4 * HD / 128, (TT * BB) / 128), blk, 2 * MST>>>(
        x, d0wih_hi, d0wih_lo, nullptr, gxe, gx, VV, 4 * HD, 2, 0, 0);
    lstm_rec_mma<<<NBLK, blk, RSMEM>>>(d0whh_hi, d0whh_lo, gx, h0, hhi, hlo, TT);

    // ---- decoder layer 1 ----
    gemm_mma<<<dim3(4 * HD / 128, (TT * BB) / 128), blk, 2 * MST>>>(
        h0, d1wih_hi, d1wih_lo, bsum_p + 8192, nullptr, gx, HD, 4 * HD, 0, 0, 0);
    lstm_rec_mma<<<NBLK, blk, RSMEM>>>(d1whh_hi, d1whh_lo, gx, h1, hhi, hlo, TT);

    // ---- output projection (time-major -> [B,T,V]) ----
    gemm_mma<<<dim3(VV / 128, (TT * BB) / 128), blk, 2 * MST>>>(
        h1, outw_hi, outw_lo, out_b, nullptr, out, HD, VV, 0, 1, 0);
}